// round 1
// baseline (speedup 1.0000x reference)
#include <cuda_runtime.h>
#include <math.h>
#include <stdint.h>

#define T_TOKENS 16384
#define HID      640
#define NQH      10
#define NKVH     2
#define HD       64
#define SEQ      512
#define BATCH    32
#define KVDIM    128   // NKVH*HD

// ---------------- scratch (device globals; no allocation allowed) ----------------
__device__ __align__(16) int8_t g_xq_q[T_TOKENS * HID];
__device__ __align__(16) int8_t g_xq_k[T_TOKENS * HID];
__device__ __align__(16) int8_t g_xq_v[T_TOKENS * HID];
__device__ __align__(16) int8_t g_xq_o[T_TOKENS * HID];
__device__ __align__(16) int8_t g_wq_q[HID * HID];
__device__ __align__(16) int8_t g_wq_k[KVDIM * HID];
__device__ __align__(16) int8_t g_wq_v[KVDIM * HID];
__device__ __align__(16) int8_t g_wq_o[HID * HID];
__device__ float g_gamma_q[T_TOKENS];
__device__ float g_gamma_k[T_TOKENS];
__device__ float g_gamma_v[T_TOKENS];
__device__ float g_gamma_o[T_TOKENS];
__device__ float g_alpha[4];
__device__ float g_qb[BATCH * NQH * SEQ * HD];   // [B, NQ, L, HD]
__device__ float g_kb[BATCH * NKVH * SEQ * HD];  // [B, NKV, L, HD]
__device__ float g_vb[BATCH * NKVH * SEQ * HD];
__device__ float g_att[T_TOKENS * HID];          // [B, L, NQ*HD]
__device__ float g_cos[SEQ * 32];
__device__ float g_sin[SEQ * 32];

// ---------------- block reduction helper ----------------
__device__ __forceinline__ float block_reduce(float v, int op, float* sm, int nwarps) {
    int lane = threadIdx.x & 31, w = threadIdx.x >> 5;
#pragma unroll
    for (int o = 16; o; o >>= 1) {
        float t = __shfl_xor_sync(0xffffffffu, v, o);
        v = op ? fmaxf(v, t) : v + t;
    }
    if (!lane) sm[w] = v;
    __syncthreads();
    if (w == 0) {
        v = (lane < nwarps) ? sm[lane] : (op ? -INFINITY : 0.0f);
#pragma unroll
        for (int o = 16; o; o >>= 1) {
            float t = __shfl_xor_sync(0xffffffffu, v, o);
            v = op ? fmaxf(v, t) : v + t;
        }
        if (!lane) sm[0] = v;
    }
    __syncthreads();
    v = sm[0];
    __syncthreads();
    return v;
}

// ---------------- weight alpha = max(mean(|w|), 1e-10) ----------------
__global__ void alpha_all(const float* __restrict__ qw, const float* __restrict__ kw,
                          const float* __restrict__ vw, const float* __restrict__ ow) {
    __shared__ float sm[32];
    int which = blockIdx.x;
    const float* w = which == 0 ? qw : which == 1 ? kw : which == 2 ? vw : ow;
    int n = (which == 1 || which == 2) ? (KVDIM * HID) : (HID * HID);
    float s = 0.0f;
    for (int i = threadIdx.x; i < n; i += 1024) s += fabsf(w[i]);
    s = block_reduce(s, 0, sm, 32);
    if (threadIdx.x == 0) g_alpha[which] = fmaxf(s / (float)n, 1e-10f);
}

// ---------------- weight ternary quant ----------------
__global__ void wquant_all(const float* __restrict__ qw, const float* __restrict__ kw,
                           const float* __restrict__ vw, const float* __restrict__ ow) {
    int idx = blockIdx.x * blockDim.x + threadIdx.x;
    const float* w; int8_t* dst; int off; int which;
    const int nQ = HID * HID, nK = KVDIM * HID;
    if (idx < nQ)                       { which = 0; w = qw; dst = g_wq_q; off = idx; }
    else if (idx < nQ + nK)             { which = 1; w = kw; dst = g_wq_k; off = idx - nQ; }
    else if (idx < nQ + 2 * nK)         { which = 2; w = vw; dst = g_wq_v; off = idx - nQ - nK; }
    else if (idx < 2 * nQ + 2 * nK)     { which = 3; w = ow; dst = g_wq_o; off = idx - nQ - 2 * nK; }
    else return;
    float a = g_alpha[which];
    float q = rintf(w[off] / a);
    q = fminf(fmaxf(q, -1.0f), 1.0f);
    dst[off] = (int8_t)q;
}

// ---------------- activation norm + int8 quant (QKV path: double rmsnorm) -------
__global__ __launch_bounds__(128) void act_quant_qkv(
    const float* __restrict__ x, const float* __restrict__ nw,
    const float* __restrict__ qg, const float* __restrict__ kg, const float* __restrict__ vg) {
    __shared__ float sm[32];
    int t = blockIdx.x, tid = threadIdx.x;
    const float* xr = x + (size_t)t * HID;
    float v[5], h[5];
    float ss = 0.0f;
#pragma unroll
    for (int i = 0; i < 5; i++) { v[i] = xr[tid + i * 128]; ss += v[i] * v[i]; }
    ss = block_reduce(ss, 0, sm, 4);
    float rinv = rsqrtf(ss / (float)HID + 1e-6f);
    float s2 = 0.0f;
#pragma unroll
    for (int i = 0; i < 5; i++) { h[i] = v[i] * rinv * nw[tid + i * 128]; s2 += h[i] * h[i]; }
    s2 = block_reduce(s2, 0, sm, 4);
    float rinv2 = rsqrtf(s2 / (float)HID + 1e-6f);

    const float* gains[3] = { qg, kg, vg };
    int8_t* dsts[3] = { g_xq_q, g_xq_k, g_xq_v };
    float* gmas[3] = { g_gamma_q, g_gamma_k, g_gamma_v };
#pragma unroll
    for (int which = 0; which < 3; which++) {
        const float* g = gains[which];
        float hq[5]; float gm = 0.0f;
#pragma unroll
        for (int i = 0; i < 5; i++) { hq[i] = h[i] * rinv2 * g[tid + i * 128]; gm = fmaxf(gm, fabsf(hq[i])); }
        gm = block_reduce(gm, 1, sm, 4);
        gm = fmaxf(gm, 1e-10f);
        float sc = 127.0f / gm;
        int8_t* dst = dsts[which] + (size_t)t * HID;
#pragma unroll
        for (int i = 0; i < 5; i++) {
            float qv = rintf(hq[i] * sc);
            qv = fminf(fmaxf(qv, -128.0f), 127.0f);
            dst[tid + i * 128] = (int8_t)qv;
        }
        if (tid == 0) gmas[which][t] = gm;
    }
}

// ---------------- activation norm + int8 quant (O path: single rmsnorm) --------
__global__ __launch_bounds__(128) void act_quant_o(const float* __restrict__ og) {
    __shared__ float sm[32];
    int t = blockIdx.x, tid = threadIdx.x;
    const float* xr = g_att + (size_t)t * HID;
    float v[5], hq[5];
    float ss = 0.0f;
#pragma unroll
    for (int i = 0; i < 5; i++) { v[i] = xr[tid + i * 128]; ss += v[i] * v[i]; }
    ss = block_reduce(ss, 0, sm, 4);
    float rinv = rsqrtf(ss / (float)HID + 1e-6f);
    float gm = 0.0f;
#pragma unroll
    for (int i = 0; i < 5; i++) { hq[i] = v[i] * rinv * og[tid + i * 128]; gm = fmaxf(gm, fabsf(hq[i])); }
    gm = block_reduce(gm, 1, sm, 4);
    gm = fmaxf(gm, 1e-10f);
    float sc = 127.0f / gm;
    int8_t* dst = g_xq_o + (size_t)t * HID;
#pragma unroll
    for (int i = 0; i < 5; i++) {
        float qv = rintf(hq[i] * sc);
        qv = fminf(fmaxf(qv, -128.0f), 127.0f);
        dst[tid + i * 128] = (int8_t)qv;
    }
    if (tid == 0) g_gamma_o[t] = gm;
}

// ---------------- dp4a GEMM: C[t,n] = dot(xq[t,:], wq[n,:]) * alpha*gamma[t]/127 -
// mode 0: scatter to [B, H, L, HD]; mode 1: token-major + residual -> d_out
__global__ __launch_bounds__(256) void gemm_dp4a(
    const int8_t* __restrict__ A, const int8_t* __restrict__ Bw,
    const float* __restrict__ gamma, const float* __restrict__ alpha_p,
    float* __restrict__ out, int mode, int nheads, const float* __restrict__ resid) {
    __shared__ __align__(16) int As[16][132];
    __shared__ __align__(16) int Bs[16][132];
    int t0 = blockIdx.x * 128;
    int n0 = blockIdx.y * 128;
    int tid = threadIdx.x;
    int tx = tid & 15, ty = tid >> 4;
    int acc[8][8];
#pragma unroll
    for (int i = 0; i < 8; i++)
#pragma unroll
        for (int j = 0; j < 8; j++) acc[i][j] = 0;

    for (int chunk = 0; chunk < 10; chunk++) {
#pragma unroll
        for (int i = 0; i < 2; i++) {
            int idx = tid * 2 + i;       // 0..511
            int x4 = idx & 3, row = idx >> 2;
            int4 a = *(const int4*)(A + (size_t)(t0 + row) * HID + chunk * 64 + x4 * 16);
            As[x4 * 4 + 0][row] = a.x; As[x4 * 4 + 1][row] = a.y;
            As[x4 * 4 + 2][row] = a.z; As[x4 * 4 + 3][row] = a.w;
            int4 b = *(const int4*)(Bw + (size_t)(n0 + row) * HID + chunk * 64 + x4 * 16);
            Bs[x4 * 4 + 0][row] = b.x; Bs[x4 * 4 + 1][row] = b.y;
            Bs[x4 * 4 + 2][row] = b.z; Bs[x4 * 4 + 3][row] = b.w;
        }
        __syncthreads();
#pragma unroll
        for (int kw = 0; kw < 16; kw++) {
            int4 a0 = *(const int4*)&As[kw][ty * 8];
            int4 a1 = *(const int4*)&As[kw][ty * 8 + 4];
            int4 b0 = *(const int4*)&Bs[kw][tx * 8];
            int4 b1 = *(const int4*)&Bs[kw][tx * 8 + 4];
            int a[8] = { a0.x, a0.y, a0.z, a0.w, a1.x, a1.y, a1.z, a1.w };
            int b[8] = { b0.x, b0.y, b0.z, b0.w, b1.x, b1.y, b1.z, b1.w };
#pragma unroll
            for (int i = 0; i < 8; i++)
#pragma unroll
                for (int j = 0; j < 8; j++)
                    acc[i][j] = __dp4a(a[i], b[j], acc[i][j]);
        }
        __syncthreads();
    }
    float alpha = *alpha_p * (1.0f / 127.0f);
#pragma unroll
    for (int i = 0; i < 8; i++) {
        int t = t0 + ty * 8 + i;
        float s = alpha * gamma[t];
#pragma unroll
        for (int j = 0; j < 8; j++) {
            int n = n0 + tx * 8 + j;
            float v = (float)acc[i][j] * s;
            if (mode == 0) {
                int b = t >> 9, l = t & 511, head = n >> 6, d = n & 63;
                out[(((size_t)b * nheads + head) * SEQ + l) * HD + d] = v;
            } else {
                out[(size_t)t * HID + n] = v + resid[(size_t)t * HID + n];
            }
        }
    }
}

// ---------------- RoPE tables (fp64 for exact angles) ----------------
__global__ void rope_tab() {
    int idx = blockIdx.x * blockDim.x + threadIdx.x;
    if (idx >= SEQ * 32) return;
    int l = idx >> 5, p = idx & 31;
    double freq = pow(500000.0, -(double)p / 32.0);
    double a = (double)l * freq;
    g_cos[idx] = (float)cos(a);
    g_sin[idx] = (float)sin(a);
}

__global__ void rope_apply(float* __restrict__ buf, int total_pairs) {
    int idx = blockIdx.x * blockDim.x + threadIdx.x;
    if (idx >= total_pairs) return;
    int p = idx & 31;
    int l = (idx >> 5) & (SEQ - 1);
    size_t base = (size_t)(idx >> 5) * HD;
    float c = g_cos[l * 32 + p], s = g_sin[l * 32 + p];
    float x1 = buf[base + 2 * p], x2 = buf[base + 2 * p + 1];
    buf[base + 2 * p]     = x1 * c - x2 * s;
    buf[base + 2 * p + 1] = x2 * c + x1 * s;
}

// ---------------- attention: flash-style, fp32, 64x64 tiles ----------------
// smem layout (floats): QsT[64][68] | KsT[64][68] | Ss[64][68] | Vs[64][64] | m[64] l[64] c[64]
#define OFF_Q  0
#define OFF_K  4352
#define OFF_S  8704
#define OFF_V  13056
#define OFF_M  17152
#define OFF_L  17216
#define OFF_C  17280
#define ATTN_SMEM_FLOATS 17344
#define ATTN_SMEM_BYTES  (ATTN_SMEM_FLOATS * 4)

__global__ __launch_bounds__(256) void attn_kernel(
    const float* __restrict__ q, const float* __restrict__ k,
    const float* __restrict__ v, float* __restrict__ out) {
    extern __shared__ float sm[];
    float* QsT = sm + OFF_Q;
    float* KsT = sm + OFF_K;
    float* Ss  = sm + OFF_S;
    float* Vs  = sm + OFF_V;
    float* mrow = sm + OFF_M;
    float* lrow = sm + OFF_L;
    float* crow = sm + OFF_C;

    int tid = threadIdx.x;
    int tx = tid & 15, ty = tid >> 4;
    int qt = blockIdx.x;
    int bh = blockIdx.y;
    int b = bh / NQH, h = bh % NQH;
    int kvh = h / (NQH / NKVH);

    const float* qb = q + (((size_t)(b * NQH + h) * SEQ) + qt * 64) * HD;
    const float* kb = k + ((size_t)(b * NKVH + kvh) * SEQ) * HD;
    const float* vb = v + ((size_t)(b * NKVH + kvh) * SEQ) * HD;

    for (int idx = tid; idx < 4096; idx += 256) {
        int d = idx & 63, r = idx >> 6;
        QsT[d * 68 + r] = qb[idx] * 0.125f;   // fold 1/sqrt(64)
    }
    if (tid < 64) { mrow[tid] = -1e30f; lrow[tid] = 0.0f; }

    float acc[4][4];
#pragma unroll
    for (int i = 0; i < 4; i++)
#pragma unroll
        for (int j = 0; j < 4; j++) acc[i][j] = 0.0f;

    for (int kt = 0; kt < 8; kt++) {
        __syncthreads();
        const float* kbt = kb + (size_t)kt * 64 * HD;
        const float* vbt = vb + (size_t)kt * 64 * HD;
        for (int idx = tid; idx < 4096; idx += 256) {
            int d = idx & 63, r = idx >> 6;
            KsT[d * 68 + r] = kbt[idx];
            Vs[idx] = vbt[idx];
        }
        __syncthreads();

        float s[4][4];
#pragma unroll
        for (int i = 0; i < 4; i++)
#pragma unroll
            for (int j = 0; j < 4; j++) s[i][j] = 0.0f;
#pragma unroll 4
        for (int d = 0; d < 64; d++) {
            float4 q4 = *(const float4*)&QsT[d * 68 + ty * 4];
            float4 k4 = *(const float4*)&KsT[d * 68 + tx * 4];
            float qa[4] = { q4.x, q4.y, q4.z, q4.w };
            float ka[4] = { k4.x, k4.y, k4.z, k4.w };
#pragma unroll
            for (int i = 0; i < 4; i++)
#pragma unroll
                for (int j = 0; j < 4; j++) s[i][j] += qa[i] * ka[j];
        }
#pragma unroll
        for (int j = 0; j < 4; j++)
#pragma unroll
            for (int i = 0; i < 4; i++)
                Ss[(tx * 4 + j) * 68 + ty * 4 + i] = s[i][j];
        __syncthreads();

        if (tid < 64) {
            int r = tid;
            float mt = -1e30f;
#pragma unroll 8
            for (int kk = 0; kk < 64; kk++) mt = fmaxf(mt, Ss[kk * 68 + r]);
            float mold = mrow[r];
            float mnew = fmaxf(mold, mt);
            float c = __expf(mold - mnew);
            float lsum = 0.0f;
#pragma unroll 8
            for (int kk = 0; kk < 64; kk++) {
                float p = __expf(Ss[kk * 68 + r] - mnew);
                Ss[kk * 68 + r] = p;
                lsum += p;
            }
            lrow[r] = lrow[r] * c + lsum;
            mrow[r] = mnew;
            crow[r] = c;
        }
        __syncthreads();

        float cr[4];
#pragma unroll
        for (int i = 0; i < 4; i++) cr[i] = crow[ty * 4 + i];
#pragma unroll
        for (int i = 0; i < 4; i++)
#pragma unroll
            for (int j = 0; j < 4; j++) acc[i][j] *= cr[i];
#pragma unroll 4
        for (int kk = 0; kk < 64; kk++) {
            float4 p4 = *(const float4*)&Ss[kk * 68 + ty * 4];
            float4 v4 = *(const float4*)&Vs[kk * 64 + tx * 4];
            float pa[4] = { p4.x, p4.y, p4.z, p4.w };
            float va[4] = { v4.x, v4.y, v4.z, v4.w };
#pragma unroll
            for (int i = 0; i < 4; i++)
#pragma unroll
                for (int j = 0; j < 4; j++) acc[i][j] += pa[i] * va[j];
        }
    }
    __syncthreads();
    float li[4];
#pragma unroll
    for (int i = 0; i < 4; i++) li[i] = 1.0f / lrow[ty * 4 + i];
#pragma unroll
    for (int i = 0; i < 4; i++) {
        int r = ty * 4 + i;
#pragma unroll
        for (int j = 0; j < 4; j++) {
            out[((size_t)b * SEQ + qt * 64 + r) * HID + h * HD + tx * 4 + j] = acc[i][j] * li[i];
        }
    }
}

// ---------------- launch ----------------
extern "C" void kernel_launch(void* const* d_in, const int* in_sizes, int n_in,
                              void* d_out, int out_size) {
    const float* x      = (const float*)d_in[0];
    const float* norm_w = (const float*)d_in[1];
    const float* q_w    = (const float*)d_in[2];
    const float* q_g    = (const float*)d_in[3];
    const float* k_w    = (const float*)d_in[4];
    const float* k_g    = (const float*)d_in[5];
    const float* v_w    = (const float*)d_in[6];
    const float* v_g    = (const float*)d_in[7];
    const float* o_w    = (const float*)d_in[8];
    const float* o_g    = (const float*)d_in[9];
    float* out = (float*)d_out;

    void *p_xq_q, *p_xq_k, *p_xq_v, *p_xq_o;
    void *p_wq_q, *p_wq_k, *p_wq_v, *p_wq_o;
    void *p_gq, *p_gk, *p_gv, *p_go, *p_alpha;
    void *p_qb, *p_kb, *p_vb, *p_att;
    cudaGetSymbolAddress(&p_xq_q, g_xq_q);  cudaGetSymbolAddress(&p_xq_k, g_xq_k);
    cudaGetSymbolAddress(&p_xq_v, g_xq_v);  cudaGetSymbolAddress(&p_xq_o, g_xq_o);
    cudaGetSymbolAddress(&p_wq_q, g_wq_q);  cudaGetSymbolAddress(&p_wq_k, g_wq_k);
    cudaGetSymbolAddress(&p_wq_v, g_wq_v);  cudaGetSymbolAddress(&p_wq_o, g_wq_o);
    cudaGetSymbolAddress(&p_gq, g_gamma_q); cudaGetSymbolAddress(&p_gk, g_gamma_k);
    cudaGetSymbolAddress(&p_gv, g_gamma_v); cudaGetSymbolAddress(&p_go, g_gamma_o);
    cudaGetSymbolAddress(&p_alpha, g_alpha);
    cudaGetSymbolAddress(&p_qb, g_qb); cudaGetSymbolAddress(&p_kb, g_kb);
    cudaGetSymbolAddress(&p_vb, g_vb); cudaGetSymbolAddress(&p_att, g_att);

    // 1. weight scales + ternary quant
    alpha_all<<<4, 1024>>>(q_w, k_w, v_w, o_w);
    wquant_all<<<(2 * HID * HID + 2 * KVDIM * HID + 255) / 256, 256>>>(q_w, k_w, v_w, o_w);

    // 2. activation double-rmsnorm + int8 quant
    act_quant_qkv<<<T_TOKENS, 128>>>(x, norm_w, q_g, k_g, v_g);

    // 3. rope tables (cheap, fp64)
    rope_tab<<<(SEQ * 32 + 255) / 256, 256>>>();

    // 4. QKV GEMMs (dp4a int8 exact)
    gemm_dp4a<<<dim3(128, 5), 256>>>((const int8_t*)p_xq_q, (const int8_t*)p_wq_q,
                                     (const float*)p_gq, (const float*)p_alpha + 0,
                                     (float*)p_qb, 0, NQH, nullptr);
    gemm_dp4a<<<dim3(128, 1), 256>>>((const int8_t*)p_xq_k, (const int8_t*)p_wq_k,
                                     (const float*)p_gk, (const float*)p_alpha + 1,
                                     (float*)p_kb, 0, NKVH, nullptr);
    gemm_dp4a<<<dim3(128, 1), 256>>>((const int8_t*)p_xq_v, (const int8_t*)p_wq_v,
                                     (const float*)p_gv, (const float*)p_alpha + 2,
                                     (float*)p_vb, 0, NKVH, nullptr);

    // 5. RoPE on q and k
    int qpairs = BATCH * NQH * SEQ * 32;
    int kpairs = BATCH * NKVH * SEQ * 32;
    rope_apply<<<(qpairs + 255) / 256, 256>>>((float*)p_qb, qpairs);
    rope_apply<<<(kpairs + 255) / 256, 256>>>((float*)p_kb, kpairs);

    // 6. attention
    cudaFuncSetAttribute(attn_kernel, cudaFuncAttributeMaxDynamicSharedMemorySize, ATTN_SMEM_BYTES);
    attn_kernel<<<dim3(8, BATCH * NQH), 256, ATTN_SMEM_BYTES>>>(
        (const float*)p_qb, (const float*)p_kb, (const float*)p_vb, (float*)p_att);

    // 7. O-proj quant + GEMM + residual
    act_quant_o<<<T_TOKENS, 128>>>(o_g);
    gemm_dp4a<<<dim3(128, 5), 256>>>((const int8_t*)p_xq_o, (const int8_t*)p_wq_o,
                                     (const float*)p_go, (const float*)p_alpha + 3,
                                     out, 1, 0, x);
}

// round 3
// speedup vs baseline: 1.6766x; 1.6766x over previous
#include <cuda_runtime.h>
#include <cuda_fp16.h>
#include <math.h>
#include <stdint.h>

#define T_TOKENS 16384
#define HID      640
#define NQH      10
#define NKVH     2
#define HD       64
#define SEQ      512
#define BATCH    32
#define KVDIM    128   // NKVH*HD

// ---------------- scratch (device globals; no allocation allowed) ----------------
__device__ __align__(16) int8_t g_xq_q[T_TOKENS * HID];
__device__ __align__(16) int8_t g_xq_k[T_TOKENS * HID];
__device__ __align__(16) int8_t g_xq_v[T_TOKENS * HID];
__device__ __align__(16) int8_t g_xq_o[T_TOKENS * HID];
__device__ __align__(16) int8_t g_wq_q[HID * HID];
__device__ __align__(16) int8_t g_wq_k[KVDIM * HID];
__device__ __align__(16) int8_t g_wq_v[KVDIM * HID];
__device__ __align__(16) int8_t g_wq_o[HID * HID];
__device__ float g_gamma_q[T_TOKENS];
__device__ float g_gamma_k[T_TOKENS];
__device__ float g_gamma_v[T_TOKENS];
__device__ float g_gamma_o[T_TOKENS];
__device__ float g_alpha[4];
__device__ float g_qb[BATCH * NQH * SEQ * HD];   // [B, NQ, L, HD]
__device__ float g_kb[BATCH * NKVH * SEQ * HD];  // [B, NKV, L, HD]
__device__ float g_vb[BATCH * NKVH * SEQ * HD];
__device__ float g_att[T_TOKENS * HID];          // [B, L, NQ*HD]
__device__ float g_cos[SEQ * 32];
__device__ float g_sin[SEQ * 32];

// ---------------- block reduction helper ----------------
__device__ __forceinline__ float block_reduce(float v, int op, float* sm, int nwarps) {
    int lane = threadIdx.x & 31, w = threadIdx.x >> 5;
#pragma unroll
    for (int o = 16; o; o >>= 1) {
        float t = __shfl_xor_sync(0xffffffffu, v, o);
        v = op ? fmaxf(v, t) : v + t;
    }
    if (!lane) sm[w] = v;
    __syncthreads();
    if (w == 0) {
        v = (lane < nwarps) ? sm[lane] : (op ? -INFINITY : 0.0f);
#pragma unroll
        for (int o = 16; o; o >>= 1) {
            float t = __shfl_xor_sync(0xffffffffu, v, o);
            v = op ? fmaxf(v, t) : v + t;
        }
        if (!lane) sm[0] = v;
    }
    __syncthreads();
    v = sm[0];
    __syncthreads();
    return v;
}

// ---------------- weight alpha = max(mean(|w|), 1e-10) ----------------
__global__ void alpha_all(const float* __restrict__ qw, const float* __restrict__ kw,
                          const float* __restrict__ vw, const float* __restrict__ ow) {
    __shared__ float sm[32];
    int which = blockIdx.x;
    const float* w = which == 0 ? qw : which == 1 ? kw : which == 2 ? vw : ow;
    int n = (which == 1 || which == 2) ? (KVDIM * HID) : (HID * HID);
    float s = 0.0f;
    for (int i = threadIdx.x; i < n; i += 1024) s += fabsf(w[i]);
    s = block_reduce(s, 0, sm, 32);
    if (threadIdx.x == 0) g_alpha[which] = fmaxf(s / (float)n, 1e-10f);
}

// ---------------- weight ternary quant ----------------
__global__ void wquant_all(const float* __restrict__ qw, const float* __restrict__ kw,
                           const float* __restrict__ vw, const float* __restrict__ ow) {
    int idx = blockIdx.x * blockDim.x + threadIdx.x;
    const float* w; int8_t* dst; int off; int which;
    const int nQ = HID * HID, nK = KVDIM * HID;
    if (idx < nQ)                       { which = 0; w = qw; dst = g_wq_q; off = idx; }
    else if (idx < nQ + nK)             { which = 1; w = kw; dst = g_wq_k; off = idx - nQ; }
    else if (idx < nQ + 2 * nK)         { which = 2; w = vw; dst = g_wq_v; off = idx - nQ - nK; }
    else if (idx < 2 * nQ + 2 * nK)     { which = 3; w = ow; dst = g_wq_o; off = idx - nQ - 2 * nK; }
    else return;
    float a = g_alpha[which];
    float q = rintf(w[off] / a);
    q = fminf(fmaxf(q, -1.0f), 1.0f);
    dst[off] = (int8_t)q;
}

// ---------------- activation norm + int8 quant (QKV path: double rmsnorm) -------
__global__ __launch_bounds__(128) void act_quant_qkv(
    const float* __restrict__ x, const float* __restrict__ nw,
    const float* __restrict__ qg, const float* __restrict__ kg, const float* __restrict__ vg) {
    __shared__ float sm[32];
    int t = blockIdx.x, tid = threadIdx.x;
    const float* xr = x + (size_t)t * HID;
    float v[5], h[5];
    float ss = 0.0f;
#pragma unroll
    for (int i = 0; i < 5; i++) { v[i] = xr[tid + i * 128]; ss += v[i] * v[i]; }
    ss = block_reduce(ss, 0, sm, 4);
    float rinv = rsqrtf(ss / (float)HID + 1e-6f);
    float s2 = 0.0f;
#pragma unroll
    for (int i = 0; i < 5; i++) { h[i] = v[i] * rinv * nw[tid + i * 128]; s2 += h[i] * h[i]; }
    s2 = block_reduce(s2, 0, sm, 4);
    float rinv2 = rsqrtf(s2 / (float)HID + 1e-6f);

    const float* gains[3] = { qg, kg, vg };
    int8_t* dsts[3] = { g_xq_q, g_xq_k, g_xq_v };
    float* gmas[3] = { g_gamma_q, g_gamma_k, g_gamma_v };
#pragma unroll
    for (int which = 0; which < 3; which++) {
        const float* g = gains[which];
        float hq[5]; float gm = 0.0f;
#pragma unroll
        for (int i = 0; i < 5; i++) { hq[i] = h[i] * rinv2 * g[tid + i * 128]; gm = fmaxf(gm, fabsf(hq[i])); }
        gm = block_reduce(gm, 1, sm, 4);
        gm = fmaxf(gm, 1e-10f);
        float sc = 127.0f / gm;
        int8_t* dst = dsts[which] + (size_t)t * HID;
#pragma unroll
        for (int i = 0; i < 5; i++) {
            float qv = rintf(hq[i] * sc);
            qv = fminf(fmaxf(qv, -128.0f), 127.0f);
            dst[tid + i * 128] = (int8_t)qv;
        }
        if (tid == 0) gmas[which][t] = gm;
    }
}

// ---------------- activation norm + int8 quant (O path: single rmsnorm) --------
__global__ __launch_bounds__(128) void act_quant_o(const float* __restrict__ og) {
    __shared__ float sm[32];
    int t = blockIdx.x, tid = threadIdx.x;
    const float* xr = g_att + (size_t)t * HID;
    float v[5], hq[5];
    float ss = 0.0f;
#pragma unroll
    for (int i = 0; i < 5; i++) { v[i] = xr[tid + i * 128]; ss += v[i] * v[i]; }
    ss = block_reduce(ss, 0, sm, 4);
    float rinv = rsqrtf(ss / (float)HID + 1e-6f);
    float gm = 0.0f;
#pragma unroll
    for (int i = 0; i < 5; i++) { hq[i] = v[i] * rinv * og[tid + i * 128]; gm = fmaxf(gm, fabsf(hq[i])); }
    gm = block_reduce(gm, 1, sm, 4);
    gm = fmaxf(gm, 1e-10f);
    float sc = 127.0f / gm;
    int8_t* dst = g_xq_o + (size_t)t * HID;
#pragma unroll
    for (int i = 0; i < 5; i++) {
        float qv = rintf(hq[i] * sc);
        qv = fminf(fmaxf(qv, -128.0f), 127.0f);
        dst[tid + i * 128] = (int8_t)qv;
    }
    if (tid == 0) g_gamma_o[t] = gm;
}

// ---------------- dp4a GEMM ----------------
__global__ __launch_bounds__(256) void gemm_dp4a(
    const int8_t* __restrict__ A, const int8_t* __restrict__ Bw,
    const float* __restrict__ gamma, const float* __restrict__ alpha_p,
    float* __restrict__ out, int mode, int nheads, const float* __restrict__ resid) {
    __shared__ __align__(16) int As[16][132];
    __shared__ __align__(16) int Bs[16][132];
    int t0 = blockIdx.x * 128;
    int n0 = blockIdx.y * 128;
    int tid = threadIdx.x;
    int tx = tid & 15, ty = tid >> 4;
    int acc[8][8];
#pragma unroll
    for (int i = 0; i < 8; i++)
#pragma unroll
        for (int j = 0; j < 8; j++) acc[i][j] = 0;

    for (int chunk = 0; chunk < 10; chunk++) {
#pragma unroll
        for (int i = 0; i < 2; i++) {
            int idx = tid * 2 + i;
            int x4 = idx & 3, row = idx >> 2;
            int4 a = *(const int4*)(A + (size_t)(t0 + row) * HID + chunk * 64 + x4 * 16);
            As[x4 * 4 + 0][row] = a.x; As[x4 * 4 + 1][row] = a.y;
            As[x4 * 4 + 2][row] = a.z; As[x4 * 4 + 3][row] = a.w;
            int4 b = *(const int4*)(Bw + (size_t)(n0 + row) * HID + chunk * 64 + x4 * 16);
            Bs[x4 * 4 + 0][row] = b.x; Bs[x4 * 4 + 1][row] = b.y;
            Bs[x4 * 4 + 2][row] = b.z; Bs[x4 * 4 + 3][row] = b.w;
        }
        __syncthreads();
#pragma unroll
        for (int kw = 0; kw < 16; kw++) {
            int4 a0 = *(const int4*)&As[kw][ty * 8];
            int4 a1 = *(const int4*)&As[kw][ty * 8 + 4];
            int4 b0 = *(const int4*)&Bs[kw][tx * 8];
            int4 b1 = *(const int4*)&Bs[kw][tx * 8 + 4];
            int a[8] = { a0.x, a0.y, a0.z, a0.w, a1.x, a1.y, a1.z, a1.w };
            int b[8] = { b0.x, b0.y, b0.z, b0.w, b1.x, b1.y, b1.z, b1.w };
#pragma unroll
            for (int i = 0; i < 8; i++)
#pragma unroll
                for (int j = 0; j < 8; j++)
                    acc[i][j] = __dp4a(a[i], b[j], acc[i][j]);
        }
        __syncthreads();
    }
    float alpha = *alpha_p * (1.0f / 127.0f);
#pragma unroll
    for (int i = 0; i < 8; i++) {
        int t = t0 + ty * 8 + i;
        float s = alpha * gamma[t];
#pragma unroll
        for (int j = 0; j < 8; j++) {
            int n = n0 + tx * 8 + j;
            float v = (float)acc[i][j] * s;
            if (mode == 0) {
                int b = t >> 9, l = t & 511, head = n >> 6, d = n & 63;
                out[(((size_t)b * nheads + head) * SEQ + l) * HD + d] = v;
            } else {
                out[(size_t)t * HID + n] = v + resid[(size_t)t * HID + n];
            }
        }
    }
}

// ---------------- RoPE ----------------
__global__ void rope_tab() {
    int idx = blockIdx.x * blockDim.x + threadIdx.x;
    if (idx >= SEQ * 32) return;
    int l = idx >> 5, p = idx & 31;
    double freq = pow(500000.0, -(double)p / 32.0);
    double a = (double)l * freq;
    g_cos[idx] = (float)cos(a);
    g_sin[idx] = (float)sin(a);
}

__global__ void rope_apply(float* __restrict__ buf, int total_pairs) {
    int idx = blockIdx.x * blockDim.x + threadIdx.x;
    if (idx >= total_pairs) return;
    int p = idx & 31;
    int l = (idx >> 5) & (SEQ - 1);
    size_t base = (size_t)(idx >> 5) * HD;
    float c = g_cos[l * 32 + p], s = g_sin[l * 32 + p];
    float x1 = buf[base + 2 * p], x2 = buf[base + 2 * p + 1];
    buf[base + 2 * p]     = x1 * c - x2 * s;
    buf[base + 2 * p + 1] = x2 * c + x1 * s;
}

// ---------------- mma helpers ----------------
__device__ __forceinline__ uint32_t smem_u32(const void* p) {
    return (uint32_t)__cvta_generic_to_shared(p);
}
__device__ __forceinline__ void ldmx4(uint32_t* r, uint32_t addr) {
    asm volatile("ldmatrix.sync.aligned.m8n8.x4.shared.b16 {%0,%1,%2,%3}, [%4];\n"
                 : "=r"(r[0]), "=r"(r[1]), "=r"(r[2]), "=r"(r[3]) : "r"(addr));
}
__device__ __forceinline__ void ldmx4t(uint32_t* r, uint32_t addr) {
    asm volatile("ldmatrix.sync.aligned.m8n8.x4.trans.shared.b16 {%0,%1,%2,%3}, [%4];\n"
                 : "=r"(r[0]), "=r"(r[1]), "=r"(r[2]), "=r"(r[3]) : "r"(addr));
}
__device__ __forceinline__ void mma_f16(float* c, const uint32_t* a, uint32_t b0, uint32_t b1) {
    asm volatile("mma.sync.aligned.m16n8k16.row.col.f32.f16.f16.f32 "
                 "{%0,%1,%2,%3}, {%4,%5,%6,%7}, {%8,%9}, {%0,%1,%2,%3};\n"
                 : "+f"(c[0]), "+f"(c[1]), "+f"(c[2]), "+f"(c[3])
                 : "r"(a[0]), "r"(a[1]), "r"(a[2]), "r"(a[3]), "r"(b0), "r"(b1));
}
__device__ __forceinline__ uint32_t pack_h2(__half x, __half y) {
    __half2 h = __halves2half2(x, y);
    return *(uint32_t*)&h;
}

// split a float into fp16 hi + fp16 lo (x ≈ hi + lo)
__device__ __forceinline__ void split_h(float x, __half& hi, __half& lo) {
    hi = __float2half_rn(x);
    lo = __float2half_rn(x - __half2float(hi));
}

// ---------------- attention: flash, fp16 split mma (fp32-accurate) --------------
// grid (SEQ/128, B*NQH), 256 threads = 8 warps, warp w owns q-rows [w*16, w*16+16)
// One 36KB smem buffer, phase-shared:
//   Q phase : Qh[128][72] at 0, Ql[128][72] at 9216 (halfs)
//   KV phase: Kh[64][72] at 0, Kl at 4608, Vh at 9216, Vl at 13824
#define SPITCH 72
__global__ __launch_bounds__(256) void attn_mma(
    const float* __restrict__ q, const float* __restrict__ k,
    const float* __restrict__ v, float* __restrict__ out) {
    __shared__ __align__(16) __half SB[18432];

    int tid = threadIdx.x;
    int warp = tid >> 5, lane = tid & 31;
    int qt = blockIdx.x;
    int bh = blockIdx.y;
    int b = bh / NQH, h = bh % NQH;
    int kvh = h / (NQH / NKVH);

    const float* qb = q + (((size_t)(b * NQH + h) * SEQ) + qt * 128) * HD;
    const float* kb = k + ((size_t)(b * NKVH + kvh) * SEQ) * HD;
    const float* vb = v + ((size_t)(b * NKVH + kvh) * SEQ) * HD;

    __half* Qh = SB;
    __half* Ql = SB + 9216;

    // load Q tile (128x64 fp32 -> fp16 hi/lo, scale 1/8 folded)
#pragma unroll
    for (int it = 0; it < 8; it++) {
        int f4 = tid + it * 256;              // float4 index, 2048 total
        int e = f4 * 4;
        int row = e >> 6, col = e & 63;
        float4 qv = *(const float4*)(qb + e);
        __half h0, l0, h1, l1, h2, l2, h3, l3;
        split_h(qv.x * 0.125f, h0, l0); split_h(qv.y * 0.125f, h1, l1);
        split_h(qv.z * 0.125f, h2, l2); split_h(qv.w * 0.125f, h3, l3);
        *(uint32_t*)&Qh[row * SPITCH + col]     = pack_h2(h0, h1);
        *(uint32_t*)&Qh[row * SPITCH + col + 2] = pack_h2(h2, h3);
        *(uint32_t*)&Ql[row * SPITCH + col]     = pack_h2(l0, l1);
        *(uint32_t*)&Ql[row * SPITCH + col + 2] = pack_h2(l2, l3);
    }
    __syncthreads();

    // persistent Q fragments (hi and lo)
    uint32_t qah[4][4], qal[4][4];
    int m0 = warp * 16;
#pragma unroll
    for (int kc = 0; kc < 4; kc++) {
        int r = m0 + (lane & 15), c = kc * 16 + (lane >> 4) * 8;
        ldmx4(qah[kc], smem_u32(&Qh[r * SPITCH + c]));
        ldmx4(qal[kc], smem_u32(&Ql[r * SPITCH + c]));
    }
    __syncthreads();   // Q buffer free for KV reuse

    __half* Kh = SB;
    __half* Kl = SB + 4608;
    __half* Vh = SB + 9216;
    __half* Vl = SB + 13824;

    float oacc[8][4];
#pragma unroll
    for (int nt = 0; nt < 8; nt++)
#pragma unroll
        for (int i = 0; i < 4; i++) oacc[nt][i] = 0.0f;
    float mrow0 = -1e30f, mrow1 = -1e30f, lrow0 = 0.0f, lrow1 = 0.0f;

    for (int kt = 0; kt < 8; kt++) {
        if (kt) __syncthreads();
        const float* kbt = kb + (size_t)kt * 64 * HD;
        const float* vbt = vb + (size_t)kt * 64 * HD;
#pragma unroll
        for (int it = 0; it < 4; it++) {
            int f4 = tid + it * 256;         // 1024 float4 each
            int e = f4 * 4;
            int row = e >> 6, col = e & 63;
            {
                float4 x4 = *(const float4*)(kbt + e);
                __half h0, l0, h1, l1, h2, l2, h3, l3;
                split_h(x4.x, h0, l0); split_h(x4.y, h1, l1);
                split_h(x4.z, h2, l2); split_h(x4.w, h3, l3);
                *(uint32_t*)&Kh[row * SPITCH + col]     = pack_h2(h0, h1);
                *(uint32_t*)&Kh[row * SPITCH + col + 2] = pack_h2(h2, h3);
                *(uint32_t*)&Kl[row * SPITCH + col]     = pack_h2(l0, l1);
                *(uint32_t*)&Kl[row * SPITCH + col + 2] = pack_h2(l2, l3);
            }
            {
                float4 x4 = *(const float4*)(vbt + e);
                __half h0, l0, h1, l1, h2, l2, h3, l3;
                split_h(x4.x, h0, l0); split_h(x4.y, h1, l1);
                split_h(x4.z, h2, l2); split_h(x4.w, h3, l3);
                *(uint32_t*)&Vh[row * SPITCH + col]     = pack_h2(h0, h1);
                *(uint32_t*)&Vh[row * SPITCH + col + 2] = pack_h2(h2, h3);
                *(uint32_t*)&Vl[row * SPITCH + col]     = pack_h2(l0, l1);
                *(uint32_t*)&Vl[row * SPITCH + col + 2] = pack_h2(l2, l3);
            }
        }
        __syncthreads();

        // S = Q@K^T with hi/lo compensation
        float sacc[8][4];
#pragma unroll
        for (int nt = 0; nt < 8; nt++)
#pragma unroll
            for (int i = 0; i < 4; i++) sacc[nt][i] = 0.0f;
        int g = lane >> 3;
        int n_off = (g >= 2) ? 8 : 0, k_off = (g & 1) * 8;
#pragma unroll
        for (int nt2 = 0; nt2 < 4; nt2++) {
#pragma unroll
            for (int kc = 0; kc < 4; kc++) {
                uint32_t kbh[4], kbl[4];
                int r = nt2 * 16 + n_off + (lane & 7), c = kc * 16 + k_off;
                ldmx4(kbh, smem_u32(&Kh[r * SPITCH + c]));
                ldmx4(kbl, smem_u32(&Kl[r * SPITCH + c]));
                mma_f16(sacc[nt2 * 2],     qah[kc], kbh[0], kbh[1]);
                mma_f16(sacc[nt2 * 2],     qah[kc], kbl[0], kbl[1]);
                mma_f16(sacc[nt2 * 2],     qal[kc], kbh[0], kbh[1]);
                mma_f16(sacc[nt2 * 2 + 1], qah[kc], kbh[2], kbh[3]);
                mma_f16(sacc[nt2 * 2 + 1], qah[kc], kbl[2], kbl[3]);
                mma_f16(sacc[nt2 * 2 + 1], qal[kc], kbh[2], kbh[3]);
            }
        }

        // online softmax; rows r0=lane/4, r1=lane/4+8
        float mx0 = -1e30f, mx1 = -1e30f;
#pragma unroll
        for (int nt = 0; nt < 8; nt++) {
            mx0 = fmaxf(mx0, fmaxf(sacc[nt][0], sacc[nt][1]));
            mx1 = fmaxf(mx1, fmaxf(sacc[nt][2], sacc[nt][3]));
        }
        mx0 = fmaxf(mx0, __shfl_xor_sync(0xffffffffu, mx0, 1));
        mx0 = fmaxf(mx0, __shfl_xor_sync(0xffffffffu, mx0, 2));
        mx1 = fmaxf(mx1, __shfl_xor_sync(0xffffffffu, mx1, 1));
        mx1 = fmaxf(mx1, __shfl_xor_sync(0xffffffffu, mx1, 2));
        float mn0 = fmaxf(mrow0, mx0), mn1 = fmaxf(mrow1, mx1);
        float e0 = __expf(mrow0 - mn0), e1 = __expf(mrow1 - mn1);
        mrow0 = mn0; mrow1 = mn1;

        float sum0 = 0.0f, sum1 = 0.0f;
        uint32_t pah[4][4], pal[4][4];
#pragma unroll
        for (int kc2 = 0; kc2 < 4; kc2++) {
            int nta = kc2 * 2, ntb = nta + 1;
            float p[8];
            p[0] = __expf(sacc[nta][0] - mn0); p[1] = __expf(sacc[nta][1] - mn0);
            p[2] = __expf(sacc[nta][2] - mn1); p[3] = __expf(sacc[nta][3] - mn1);
            p[4] = __expf(sacc[ntb][0] - mn0); p[5] = __expf(sacc[ntb][1] - mn0);
            p[6] = __expf(sacc[ntb][2] - mn1); p[7] = __expf(sacc[ntb][3] - mn1);
            __half ph[8], pl[8];
#pragma unroll
            for (int i = 0; i < 8; i++) split_h(p[i], ph[i], pl[i]);
            sum0 += p[0] + p[1] + p[4] + p[5];
            sum1 += p[2] + p[3] + p[6] + p[7];
            pah[kc2][0] = pack_h2(ph[0], ph[1]); pal[kc2][0] = pack_h2(pl[0], pl[1]);
            pah[kc2][1] = pack_h2(ph[2], ph[3]); pal[kc2][1] = pack_h2(pl[2], pl[3]);
            pah[kc2][2] = pack_h2(ph[4], ph[5]); pal[kc2][2] = pack_h2(pl[4], pl[5]);
            pah[kc2][3] = pack_h2(ph[6], ph[7]); pal[kc2][3] = pack_h2(pl[6], pl[7]);
        }
        sum0 += __shfl_xor_sync(0xffffffffu, sum0, 1);
        sum0 += __shfl_xor_sync(0xffffffffu, sum0, 2);
        sum1 += __shfl_xor_sync(0xffffffffu, sum1, 1);
        sum1 += __shfl_xor_sync(0xffffffffu, sum1, 2);
        lrow0 = lrow0 * e0 + sum0;
        lrow1 = lrow1 * e1 + sum1;

#pragma unroll
        for (int nt = 0; nt < 8; nt++) {
            oacc[nt][0] *= e0; oacc[nt][1] *= e0;
            oacc[nt][2] *= e1; oacc[nt][3] *= e1;
        }

        // O += P @ V with hi/lo compensation
#pragma unroll
        for (int kc2 = 0; kc2 < 4; kc2++) {
#pragma unroll
            for (int nt2 = 0; nt2 < 4; nt2++) {
                uint32_t vbh[4], vbl[4];
                int r = kc2 * 16 + (g & 1) * 8 + (lane & 7);
                int c = nt2 * 16 + ((g >= 2) ? 8 : 0);
                ldmx4t(vbh, smem_u32(&Vh[r * SPITCH + c]));
                ldmx4t(vbl, smem_u32(&Vl[r * SPITCH + c]));
                mma_f16(oacc[nt2 * 2],     pah[kc2], vbh[0], vbh[1]);
                mma_f16(oacc[nt2 * 2],     pah[kc2], vbl[0], vbl[1]);
                mma_f16(oacc[nt2 * 2],     pal[kc2], vbh[0], vbh[1]);
                mma_f16(oacc[nt2 * 2 + 1], pah[kc2], vbh[2], vbh[3]);
                mma_f16(oacc[nt2 * 2 + 1], pah[kc2], vbl[2], vbl[3]);
                mma_f16(oacc[nt2 * 2 + 1], pal[kc2], vbh[2], vbh[3]);
            }
        }
    }

    float inv0 = 1.0f / lrow0, inv1 = 1.0f / lrow1;
    int r0 = qt * 128 + m0 + (lane >> 2);
    int r1 = r0 + 8;
#pragma unroll
    for (int nt = 0; nt < 8; nt++) {
        int col = h * HD + nt * 8 + (lane & 3) * 2;
        float2 v0 = make_float2(oacc[nt][0] * inv0, oacc[nt][1] * inv0);
        float2 v1 = make_float2(oacc[nt][2] * inv1, oacc[nt][3] * inv1);
        *(float2*)&out[((size_t)b * SEQ + r0) * HID + col] = v0;
        *(float2*)&out[((size_t)b * SEQ + r1) * HID + col] = v1;
    }
}

// ---------------- launch ----------------
extern "C" void kernel_launch(void* const* d_in, const int* in_sizes, int n_in,
                              void* d_out, int out_size) {
    const float* x      = (const float*)d_in[0];
    const float* norm_w = (const float*)d_in[1];
    const float* q_w    = (const float*)d_in[2];
    const float* q_g    = (const float*)d_in[3];
    const float* k_w    = (const float*)d_in[4];
    const float* k_g    = (const float*)d_in[5];
    const float* v_w    = (const float*)d_in[6];
    const float* v_g    = (const float*)d_in[7];
    const float* o_w    = (const float*)d_in[8];
    const float* o_g    = (const float*)d_in[9];
    float* out = (float*)d_out;

    void *p_xq_q, *p_xq_k, *p_xq_v, *p_xq_o;
    void *p_wq_q, *p_wq_k, *p_wq_v, *p_wq_o;
    void *p_gq, *p_gk, *p_gv, *p_go, *p_alpha;
    void *p_qb, *p_kb, *p_vb, *p_att;
    cudaGetSymbolAddress(&p_xq_q, g_xq_q);  cudaGetSymbolAddress(&p_xq_k, g_xq_k);
    cudaGetSymbolAddress(&p_xq_v, g_xq_v);  cudaGetSymbolAddress(&p_xq_o, g_xq_o);
    cudaGetSymbolAddress(&p_wq_q, g_wq_q);  cudaGetSymbolAddress(&p_wq_k, g_wq_k);
    cudaGetSymbolAddress(&p_wq_v, g_wq_v);  cudaGetSymbolAddress(&p_wq_o, g_wq_o);
    cudaGetSymbolAddress(&p_gq, g_gamma_q); cudaGetSymbolAddress(&p_gk, g_gamma_k);
    cudaGetSymbolAddress(&p_gv, g_gamma_v); cudaGetSymbolAddress(&p_go, g_gamma_o);
    cudaGetSymbolAddress(&p_alpha, g_alpha);
    cudaGetSymbolAddress(&p_qb, g_qb); cudaGetSymbolAddress(&p_kb, g_kb);
    cudaGetSymbolAddress(&p_vb, g_vb); cudaGetSymbolAddress(&p_att, g_att);

    // 1. weight scales + ternary quant
    alpha_all<<<4, 1024>>>(q_w, k_w, v_w, o_w);
    wquant_all<<<(2 * HID * HID + 2 * KVDIM * HID + 255) / 256, 256>>>(q_w, k_w, v_w, o_w);

    // 2. activation double-rmsnorm + int8 quant
    act_quant_qkv<<<T_TOKENS, 128>>>(x, norm_w, q_g, k_g, v_g);

    // 3. rope tables
    rope_tab<<<(SEQ * 32 + 255) / 256, 256>>>();

    // 4. QKV GEMMs (dp4a int8 exact)
    gemm_dp4a<<<dim3(128, 5), 256>>>((const int8_t*)p_xq_q, (const int8_t*)p_wq_q,
                                     (const float*)p_gq, (const float*)p_alpha + 0,
                                     (float*)p_qb, 0, NQH, nullptr);
    gemm_dp4a<<<dim3(128, 1), 256>>>((const int8_t*)p_xq_k, (const int8_t*)p_wq_k,
                                     (const float*)p_gk, (const float*)p_alpha + 1,
                                     (float*)p_kb, 0, NKVH, nullptr);
    gemm_dp4a<<<dim3(128, 1), 256>>>((const int8_t*)p_xq_v, (const int8_t*)p_wq_v,
                                     (const float*)p_gv, (const float*)p_alpha + 2,
                                     (float*)p_vb, 0, NKVH, nullptr);

    // 5. RoPE on q and k
    int qpairs = BATCH * NQH * SEQ * 32;
    int kpairs = BATCH * NKVH * SEQ * 32;
    rope_apply<<<(qpairs + 255) / 256, 256>>>((float*)p_qb, qpairs);
    rope_apply<<<(kpairs + 255) / 256, 256>>>((float*)p_kb, kpairs);

    // 6. attention (fp16 split mma flash)
    attn_mma<<<dim3(SEQ / 128, BATCH * NQH), 256>>>(
        (const float*)p_qb, (const float*)p_kb, (const float*)p_vb, (float*)p_att);

    // 7. O-proj quant + GEMM + residual
    act_quant_o<<<T_TOKENS, 128>>>(o_g);
    gemm_dp4a<<<dim3(128, 5), 256>>>((const int8_t*)p_xq_o, (const int8_t*)p_wq_o,
                                     (const float*)p_go, (const float*)p_alpha + 3,
                                     out, 1, 0, x);
}

// round 4
// speedup vs baseline: 2.0468x; 1.2208x over previous
#include <cuda_runtime.h>
#include <cuda_fp16.h>
#include <math.h>
#include <stdint.h>

#define T_TOKENS 16384
#define HID      640
#define NQH      10
#define NKVH     2
#define HD       64
#define SEQ      512
#define BATCH    32
#define KVDIM    128   // NKVH*HD

// ---------------- scratch (device globals; no allocation allowed) ----------------
__device__ __align__(16) int8_t g_xq_q[T_TOKENS * HID];
__device__ __align__(16) int8_t g_xq_k[T_TOKENS * HID];
__device__ __align__(16) int8_t g_xq_v[T_TOKENS * HID];
__device__ __align__(16) int8_t g_xq_o[T_TOKENS * HID];
__device__ __align__(16) int8_t g_wq_q[HID * HID];
__device__ __align__(16) int8_t g_wq_k[KVDIM * HID];
__device__ __align__(16) int8_t g_wq_v[KVDIM * HID];
__device__ __align__(16) int8_t g_wq_o[HID * HID];
__device__ float g_gamma_q[T_TOKENS];
__device__ float g_gamma_k[T_TOKENS];
__device__ float g_gamma_v[T_TOKENS];
__device__ float g_gamma_o[T_TOKENS];
__device__ float g_alpha[4];
__device__ float g_qb[BATCH * NQH * SEQ * HD];   // [B, NQ, L, HD]
__device__ float g_kb[BATCH * NKVH * SEQ * HD];  // [B, NKV, L, HD]
__device__ float g_vb[BATCH * NKVH * SEQ * HD];
__device__ float g_att[T_TOKENS * HID];          // [B, L, NQ*HD]
__device__ float g_cos[SEQ * 32];
__device__ float g_sin[SEQ * 32];

// ---------------- block reduction helper ----------------
__device__ __forceinline__ float block_reduce(float v, int op, float* sm, int nwarps) {
    int lane = threadIdx.x & 31, w = threadIdx.x >> 5;
#pragma unroll
    for (int o = 16; o; o >>= 1) {
        float t = __shfl_xor_sync(0xffffffffu, v, o);
        v = op ? fmaxf(v, t) : v + t;
    }
    if (!lane) sm[w] = v;
    __syncthreads();
    if (w == 0) {
        v = (lane < nwarps) ? sm[lane] : (op ? -INFINITY : 0.0f);
#pragma unroll
        for (int o = 16; o; o >>= 1) {
            float t = __shfl_xor_sync(0xffffffffu, v, o);
            v = op ? fmaxf(v, t) : v + t;
        }
        if (!lane) sm[0] = v;
    }
    __syncthreads();
    v = sm[0];
    __syncthreads();
    return v;
}

// ---------------- weight alpha = max(mean(|w|), 1e-10) ----------------
__global__ void alpha_all(const float* __restrict__ qw, const float* __restrict__ kw,
                          const float* __restrict__ vw, const float* __restrict__ ow) {
    __shared__ float sm[32];
    int which = blockIdx.x;
    const float* w = which == 0 ? qw : which == 1 ? kw : which == 2 ? vw : ow;
    int n = (which == 1 || which == 2) ? (KVDIM * HID) : (HID * HID);
    float s = 0.0f;
    for (int i = threadIdx.x; i < n; i += 1024) s += fabsf(w[i]);
    s = block_reduce(s, 0, sm, 32);
    if (threadIdx.x == 0) g_alpha[which] = fmaxf(s / (float)n, 1e-10f);
}

// ---------------- weight ternary quant ----------------
__global__ void wquant_all(const float* __restrict__ qw, const float* __restrict__ kw,
                           const float* __restrict__ vw, const float* __restrict__ ow) {
    int idx = blockIdx.x * blockDim.x + threadIdx.x;
    const float* w; int8_t* dst; int off; int which;
    const int nQ = HID * HID, nK = KVDIM * HID;
    if (idx < nQ)                       { which = 0; w = qw; dst = g_wq_q; off = idx; }
    else if (idx < nQ + nK)             { which = 1; w = kw; dst = g_wq_k; off = idx - nQ; }
    else if (idx < nQ + 2 * nK)         { which = 2; w = vw; dst = g_wq_v; off = idx - nQ - nK; }
    else if (idx < 2 * nQ + 2 * nK)     { which = 3; w = ow; dst = g_wq_o; off = idx - nQ - 2 * nK; }
    else return;
    float a = g_alpha[which];
    float q = rintf(w[off] / a);
    q = fminf(fmaxf(q, -1.0f), 1.0f);
    dst[off] = (int8_t)q;
}

// ---------------- activation norm + int8 quant (QKV path: double rmsnorm) -------
__global__ __launch_bounds__(128) void act_quant_qkv(
    const float* __restrict__ x, const float* __restrict__ nw,
    const float* __restrict__ qg, const float* __restrict__ kg, const float* __restrict__ vg) {
    __shared__ float sm[32];
    int t = blockIdx.x, tid = threadIdx.x;
    const float* xr = x + (size_t)t * HID;
    float v[5], h[5];
    float ss = 0.0f;
#pragma unroll
    for (int i = 0; i < 5; i++) { v[i] = xr[tid + i * 128]; ss += v[i] * v[i]; }
    ss = block_reduce(ss, 0, sm, 4);
    float rinv = rsqrtf(ss / (float)HID + 1e-6f);
    float s2 = 0.0f;
#pragma unroll
    for (int i = 0; i < 5; i++) { h[i] = v[i] * rinv * nw[tid + i * 128]; s2 += h[i] * h[i]; }
    s2 = block_reduce(s2, 0, sm, 4);
    float rinv2 = rsqrtf(s2 / (float)HID + 1e-6f);

    const float* gains[3] = { qg, kg, vg };
    int8_t* dsts[3] = { g_xq_q, g_xq_k, g_xq_v };
    float* gmas[3] = { g_gamma_q, g_gamma_k, g_gamma_v };
#pragma unroll
    for (int which = 0; which < 3; which++) {
        const float* g = gains[which];
        float hq[5]; float gm = 0.0f;
#pragma unroll
        for (int i = 0; i < 5; i++) { hq[i] = h[i] * rinv2 * g[tid + i * 128]; gm = fmaxf(gm, fabsf(hq[i])); }
        gm = block_reduce(gm, 1, sm, 4);
        gm = fmaxf(gm, 1e-10f);
        float sc = 127.0f / gm;
        int8_t* dst = dsts[which] + (size_t)t * HID;
#pragma unroll
        for (int i = 0; i < 5; i++) {
            float qv = rintf(hq[i] * sc);
            qv = fminf(fmaxf(qv, -128.0f), 127.0f);
            dst[tid + i * 128] = (int8_t)qv;
        }
        if (tid == 0) gmas[which][t] = gm;
    }
}

// ---------------- activation norm + int8 quant (O path: single rmsnorm) --------
__global__ __launch_bounds__(128) void act_quant_o(const float* __restrict__ og) {
    __shared__ float sm[32];
    int t = blockIdx.x, tid = threadIdx.x;
    const float* xr = g_att + (size_t)t * HID;
    float v[5], hq[5];
    float ss = 0.0f;
#pragma unroll
    for (int i = 0; i < 5; i++) { v[i] = xr[tid + i * 128]; ss += v[i] * v[i]; }
    ss = block_reduce(ss, 0, sm, 4);
    float rinv = rsqrtf(ss / (float)HID + 1e-6f);
    float gm = 0.0f;
#pragma unroll
    for (int i = 0; i < 5; i++) { hq[i] = v[i] * rinv * og[tid + i * 128]; gm = fmaxf(gm, fabsf(hq[i])); }
    gm = block_reduce(gm, 1, sm, 4);
    gm = fmaxf(gm, 1e-10f);
    float sc = 127.0f / gm;
    int8_t* dst = g_xq_o + (size_t)t * HID;
#pragma unroll
    for (int i = 0; i < 5; i++) {
        float qv = rintf(hq[i] * sc);
        qv = fminf(fmaxf(qv, -128.0f), 127.0f);
        dst[tid + i * 128] = (int8_t)qv;
    }
    if (tid == 0) g_gamma_o[t] = gm;
}

// ---------------- mma helpers ----------------
__device__ __forceinline__ uint32_t smem_u32(const void* p) {
    return (uint32_t)__cvta_generic_to_shared(p);
}
__device__ __forceinline__ void ldmx4(uint32_t* r, uint32_t addr) {
    asm volatile("ldmatrix.sync.aligned.m8n8.x4.shared.b16 {%0,%1,%2,%3}, [%4];\n"
                 : "=r"(r[0]), "=r"(r[1]), "=r"(r[2]), "=r"(r[3]) : "r"(addr));
}
__device__ __forceinline__ void ldmx4t(uint32_t* r, uint32_t addr) {
    asm volatile("ldmatrix.sync.aligned.m8n8.x4.trans.shared.b16 {%0,%1,%2,%3}, [%4];\n"
                 : "=r"(r[0]), "=r"(r[1]), "=r"(r[2]), "=r"(r[3]) : "r"(addr));
}
__device__ __forceinline__ void mma_f16(float* c, const uint32_t* a, uint32_t b0, uint32_t b1) {
    asm volatile("mma.sync.aligned.m16n8k16.row.col.f32.f16.f16.f32 "
                 "{%0,%1,%2,%3}, {%4,%5,%6,%7}, {%8,%9}, {%0,%1,%2,%3};\n"
                 : "+f"(c[0]), "+f"(c[1]), "+f"(c[2]), "+f"(c[3])
                 : "r"(a[0]), "r"(a[1]), "r"(a[2]), "r"(a[3]), "r"(b0), "r"(b1));
}
__device__ __forceinline__ void mma_s8(int* c, const uint32_t* a, uint32_t b0, uint32_t b1) {
    asm volatile("mma.sync.aligned.m16n8k32.row.col.s32.s8.s8.s32 "
                 "{%0,%1,%2,%3}, {%4,%5,%6,%7}, {%8,%9}, {%0,%1,%2,%3};\n"
                 : "+r"(c[0]), "+r"(c[1]), "+r"(c[2]), "+r"(c[3])
                 : "r"(a[0]), "r"(a[1]), "r"(a[2]), "r"(a[3]), "r"(b0), "r"(b1));
}
__device__ __forceinline__ uint32_t pack_h2(__half x, __half y) {
    __half2 h = __halves2half2(x, y);
    return *(uint32_t*)&h;
}
__device__ __forceinline__ void split_h(float x, __half& hi, __half& lo) {
    hi = __float2half_rn(x);
    lo = __float2half_rn(x - __half2float(hi));
}

// ---------------- int8 tensor-core GEMM (bit-exact vs dp4a) --------------------
// 128x128 tile, 256 threads = 8 warps in 4x2 (m x n); warp tile 32x64.
// K staged in 5 chunks of 128 bytes. smem pitch 144 B (LDSM conflict-free).
#define GP 144
__global__ __launch_bounds__(256) void gemm_imma(
    const int8_t* __restrict__ A, const int8_t* __restrict__ Bw,
    const float* __restrict__ gamma, const float* __restrict__ alpha_p,
    float* __restrict__ out, int mode, int nheads, const float* __restrict__ resid) {
    __shared__ __align__(16) int8_t As[128 * GP];
    __shared__ __align__(16) int8_t Bs[128 * GP];
    int t0 = blockIdx.x * 128;
    int n0 = blockIdx.y * 128;
    int tid = threadIdx.x, warp = tid >> 5, lane = tid & 31;
    int wm = warp >> 1, wn = warp & 1;

    int acc[2][8][4];
#pragma unroll
    for (int mt = 0; mt < 2; mt++)
#pragma unroll
        for (int nt = 0; nt < 8; nt++)
#pragma unroll
            for (int i = 0; i < 4; i++) acc[mt][nt][i] = 0;

    for (int chunk = 0; chunk < 5; chunk++) {
#pragma unroll
        for (int i = 0; i < 4; i++) {
            int idx = tid + i * 256;          // 1024 int4 slots
            int row = idx >> 3, seg = idx & 7;
            *(int4*)&As[row * GP + seg * 16] =
                *(const int4*)&A[(size_t)(t0 + row) * HID + chunk * 128 + seg * 16];
            *(int4*)&Bs[row * GP + seg * 16] =
                *(const int4*)&Bw[(size_t)(n0 + row) * HID + chunk * 128 + seg * 16];
        }
        __syncthreads();
#pragma unroll
        for (int ks = 0; ks < 4; ks++) {      // 4 k-steps of 32 bytes
            uint32_t af[2][4];
#pragma unroll
            for (int mt = 0; mt < 2; mt++)
                ldmx4(af[mt], smem_u32(&As[(wm * 32 + mt * 16 + (lane & 15)) * GP +
                                            ks * 32 + (lane >> 4) * 16]));
#pragma unroll
            for (int np = 0; np < 4; np++) {  // pairs of n-tiles (16 cols)
                uint32_t bf[4];
                ldmx4(bf, smem_u32(&Bs[(wn * 64 + np * 16 + (lane & 15)) * GP +
                                        ks * 32 + (lane >> 4) * 16]));
#pragma unroll
                for (int mt = 0; mt < 2; mt++) {
                    mma_s8(acc[mt][np * 2],     af[mt], bf[0], bf[2]);
                    mma_s8(acc[mt][np * 2 + 1], af[mt], bf[1], bf[3]);
                }
            }
        }
        __syncthreads();
    }

    float alpha = *alpha_p * (1.0f / 127.0f);
#pragma unroll
    for (int mt = 0; mt < 2; mt++) {
        int r0 = t0 + wm * 32 + mt * 16 + (lane >> 2);
        int r1 = r0 + 8;
        float s0 = alpha * gamma[r0];
        float s1 = alpha * gamma[r1];
#pragma unroll
        for (int nt = 0; nt < 8; nt++) {
            int n = n0 + wn * 64 + nt * 8 + (lane & 3) * 2;
            float v00 = (float)acc[mt][nt][0] * s0, v01 = (float)acc[mt][nt][1] * s0;
            float v10 = (float)acc[mt][nt][2] * s1, v11 = (float)acc[mt][nt][3] * s1;
            if (mode == 0) {
                int head = n >> 6, d = n & 63;
                int b0i = r0 >> 9, l0 = r0 & 511;
                int b1i = r1 >> 9, l1 = r1 & 511;
                *(float2*)&out[(((size_t)b0i * nheads + head) * SEQ + l0) * HD + d] =
                    make_float2(v00, v01);
                *(float2*)&out[(((size_t)b1i * nheads + head) * SEQ + l1) * HD + d] =
                    make_float2(v10, v11);
            } else {
                const float* rr0 = resid + (size_t)r0 * HID + n;
                const float* rr1 = resid + (size_t)r1 * HID + n;
                *(float2*)&out[(size_t)r0 * HID + n] = make_float2(v00 + rr0[0], v01 + rr0[1]);
                *(float2*)&out[(size_t)r1 * HID + n] = make_float2(v10 + rr1[0], v11 + rr1[1]);
            }
        }
    }
}

// ---------------- RoPE ----------------
__global__ void rope_tab() {
    int idx = blockIdx.x * blockDim.x + threadIdx.x;
    if (idx >= SEQ * 32) return;
    int l = idx >> 5, p = idx & 31;
    double freq = pow(500000.0, -(double)p / 32.0);
    double a = (double)l * freq;
    g_cos[idx] = (float)cos(a);
    g_sin[idx] = (float)sin(a);
}

__global__ void rope_apply(float* __restrict__ buf, int total_pairs) {
    int idx = blockIdx.x * blockDim.x + threadIdx.x;
    if (idx >= total_pairs) return;
    int p = idx & 31;
    int l = (idx >> 5) & (SEQ - 1);
    size_t base = (size_t)(idx >> 5) * HD;
    float c = g_cos[l * 32 + p], s = g_sin[l * 32 + p];
    float x1 = buf[base + 2 * p], x2 = buf[base + 2 * p + 1];
    buf[base + 2 * p]     = x1 * c - x2 * s;
    buf[base + 2 * p + 1] = x2 * c + x1 * s;
}

// ---------------- attention: flash, fp16 split mma (fp32-accurate) --------------
#define SPITCH 72
__global__ __launch_bounds__(256) void attn_mma(
    const float* __restrict__ q, const float* __restrict__ k,
    const float* __restrict__ v, float* __restrict__ out) {
    __shared__ __align__(16) __half SB[18432];

    int tid = threadIdx.x;
    int warp = tid >> 5, lane = tid & 31;
    int qt = blockIdx.x;
    int bh = blockIdx.y;
    int b = bh / NQH, h = bh % NQH;
    int kvh = h / (NQH / NKVH);

    const float* qb = q + (((size_t)(b * NQH + h) * SEQ) + qt * 128) * HD;
    const float* kb = k + ((size_t)(b * NKVH + kvh) * SEQ) * HD;
    const float* vb = v + ((size_t)(b * NKVH + kvh) * SEQ) * HD;

    __half* Qh = SB;
    __half* Ql = SB + 9216;

#pragma unroll
    for (int it = 0; it < 8; it++) {
        int f4 = tid + it * 256;
        int e = f4 * 4;
        int row = e >> 6, col = e & 63;
        float4 qv = *(const float4*)(qb + e);
        __half h0, l0, h1, l1, h2, l2, h3, l3;
        split_h(qv.x * 0.125f, h0, l0); split_h(qv.y * 0.125f, h1, l1);
        split_h(qv.z * 0.125f, h2, l2); split_h(qv.w * 0.125f, h3, l3);
        *(uint32_t*)&Qh[row * SPITCH + col]     = pack_h2(h0, h1);
        *(uint32_t*)&Qh[row * SPITCH + col + 2] = pack_h2(h2, h3);
        *(uint32_t*)&Ql[row * SPITCH + col]     = pack_h2(l0, l1);
        *(uint32_t*)&Ql[row * SPITCH + col + 2] = pack_h2(l2, l3);
    }
    __syncthreads();

    uint32_t qah[4][4], qal[4][4];
    int m0 = warp * 16;
#pragma unroll
    for (int kc = 0; kc < 4; kc++) {
        int r = m0 + (lane & 15), c = kc * 16 + (lane >> 4) * 8;
        ldmx4(qah[kc], smem_u32(&Qh[r * SPITCH + c]));
        ldmx4(qal[kc], smem_u32(&Ql[r * SPITCH + c]));
    }
    __syncthreads();

    __half* Kh = SB;
    __half* Kl = SB + 4608;
    __half* Vh = SB + 9216;
    __half* Vl = SB + 13824;

    float oacc[8][4];
#pragma unroll
    for (int nt = 0; nt < 8; nt++)
#pragma unroll
        for (int i = 0; i < 4; i++) oacc[nt][i] = 0.0f;
    float mrow0 = -1e30f, mrow1 = -1e30f, lrow0 = 0.0f, lrow1 = 0.0f;

    for (int kt = 0; kt < 8; kt++) {
        if (kt) __syncthreads();
        const float* kbt = kb + (size_t)kt * 64 * HD;
        const float* vbt = vb + (size_t)kt * 64 * HD;
#pragma unroll
        for (int it = 0; it < 4; it++) {
            int f4 = tid + it * 256;
            int e = f4 * 4;
            int row = e >> 6, col = e & 63;
            {
                float4 x4 = *(const float4*)(kbt + e);
                __half h0, l0, h1, l1, h2, l2, h3, l3;
                split_h(x4.x, h0, l0); split_h(x4.y, h1, l1);
                split_h(x4.z, h2, l2); split_h(x4.w, h3, l3);
                *(uint32_t*)&Kh[row * SPITCH + col]     = pack_h2(h0, h1);
                *(uint32_t*)&Kh[row * SPITCH + col + 2] = pack_h2(h2, h3);
                *(uint32_t*)&Kl[row * SPITCH + col]     = pack_h2(l0, l1);
                *(uint32_t*)&Kl[row * SPITCH + col + 2] = pack_h2(l2, l3);
            }
            {
                float4 x4 = *(const float4*)(vbt + e);
                __half h0, l0, h1, l1, h2, l2, h3, l3;
                split_h(x4.x, h0, l0); split_h(x4.y, h1, l1);
                split_h(x4.z, h2, l2); split_h(x4.w, h3, l3);
                *(uint32_t*)&Vh[row * SPITCH + col]     = pack_h2(h0, h1);
                *(uint32_t*)&Vh[row * SPITCH + col + 2] = pack_h2(h2, h3);
                *(uint32_t*)&Vl[row * SPITCH + col]     = pack_h2(l0, l1);
                *(uint32_t*)&Vl[row * SPITCH + col + 2] = pack_h2(l2, l3);
            }
        }
        __syncthreads();

        float sacc[8][4];
#pragma unroll
        for (int nt = 0; nt < 8; nt++)
#pragma unroll
            for (int i = 0; i < 4; i++) sacc[nt][i] = 0.0f;
        int g = lane >> 3;
        int n_off = (g >= 2) ? 8 : 0, k_off = (g & 1) * 8;
#pragma unroll
        for (int nt2 = 0; nt2 < 4; nt2++) {
#pragma unroll
            for (int kc = 0; kc < 4; kc++) {
                uint32_t kbh[4], kbl[4];
                int r = nt2 * 16 + n_off + (lane & 7), c = kc * 16 + k_off;
                ldmx4(kbh, smem_u32(&Kh[r * SPITCH + c]));
                ldmx4(kbl, smem_u32(&Kl[r * SPITCH + c]));
                mma_f16(sacc[nt2 * 2],     qah[kc], kbh[0], kbh[1]);
                mma_f16(sacc[nt2 * 2],     qah[kc], kbl[0], kbl[1]);
                mma_f16(sacc[nt2 * 2],     qal[kc], kbh[0], kbh[1]);
                mma_f16(sacc[nt2 * 2 + 1], qah[kc], kbh[2], kbh[3]);
                mma_f16(sacc[nt2 * 2 + 1], qah[kc], kbl[2], kbl[3]);
                mma_f16(sacc[nt2 * 2 + 1], qal[kc], kbh[2], kbh[3]);
            }
        }

        float mx0 = -1e30f, mx1 = -1e30f;
#pragma unroll
        for (int nt = 0; nt < 8; nt++) {
            mx0 = fmaxf(mx0, fmaxf(sacc[nt][0], sacc[nt][1]));
            mx1 = fmaxf(mx1, fmaxf(sacc[nt][2], sacc[nt][3]));
        }
        mx0 = fmaxf(mx0, __shfl_xor_sync(0xffffffffu, mx0, 1));
        mx0 = fmaxf(mx0, __shfl_xor_sync(0xffffffffu, mx0, 2));
        mx1 = fmaxf(mx1, __shfl_xor_sync(0xffffffffu, mx1, 1));
        mx1 = fmaxf(mx1, __shfl_xor_sync(0xffffffffu, mx1, 2));
        float mn0 = fmaxf(mrow0, mx0), mn1 = fmaxf(mrow1, mx1);
        float e0 = __expf(mrow0 - mn0), e1 = __expf(mrow1 - mn1);
        mrow0 = mn0; mrow1 = mn1;

        float sum0 = 0.0f, sum1 = 0.0f;
        uint32_t pah[4][4], pal[4][4];
#pragma unroll
        for (int kc2 = 0; kc2 < 4; kc2++) {
            int nta = kc2 * 2, ntb = nta + 1;
            float p[8];
            p[0] = __expf(sacc[nta][0] - mn0); p[1] = __expf(sacc[nta][1] - mn0);
            p[2] = __expf(sacc[nta][2] - mn1); p[3] = __expf(sacc[nta][3] - mn1);
            p[4] = __expf(sacc[ntb][0] - mn0); p[5] = __expf(sacc[ntb][1] - mn0);
            p[6] = __expf(sacc[ntb][2] - mn1); p[7] = __expf(sacc[ntb][3] - mn1);
            __half ph[8], pl[8];
#pragma unroll
            for (int i = 0; i < 8; i++) split_h(p[i], ph[i], pl[i]);
            sum0 += p[0] + p[1] + p[4] + p[5];
            sum1 += p[2] + p[3] + p[6] + p[7];
            pah[kc2][0] = pack_h2(ph[0], ph[1]); pal[kc2][0] = pack_h2(pl[0], pl[1]);
            pah[kc2][1] = pack_h2(ph[2], ph[3]); pal[kc2][1] = pack_h2(pl[2], pl[3]);
            pah[kc2][2] = pack_h2(ph[4], ph[5]); pal[kc2][2] = pack_h2(pl[4], pl[5]);
            pah[kc2][3] = pack_h2(ph[6], ph[7]); pal[kc2][3] = pack_h2(pl[6], pl[7]);
        }
        sum0 += __shfl_xor_sync(0xffffffffu, sum0, 1);
        sum0 += __shfl_xor_sync(0xffffffffu, sum0, 2);
        sum1 += __shfl_xor_sync(0xffffffffu, sum1, 1);
        sum1 += __shfl_xor_sync(0xffffffffu, sum1, 2);
        lrow0 = lrow0 * e0 + sum0;
        lrow1 = lrow1 * e1 + sum1;

#pragma unroll
        for (int nt = 0; nt < 8; nt++) {
            oacc[nt][0] *= e0; oacc[nt][1] *= e0;
            oacc[nt][2] *= e1; oacc[nt][3] *= e1;
        }

#pragma unroll
        for (int kc2 = 0; kc2 < 4; kc2++) {
#pragma unroll
            for (int nt2 = 0; nt2 < 4; nt2++) {
                uint32_t vbh[4], vbl[4];
                int r = kc2 * 16 + (g & 1) * 8 + (lane & 7);
                int c = nt2 * 16 + ((g >= 2) ? 8 : 0);
                ldmx4t(vbh, smem_u32(&Vh[r * SPITCH + c]));
                ldmx4t(vbl, smem_u32(&Vl[r * SPITCH + c]));
                mma_f16(oacc[nt2 * 2],     pah[kc2], vbh[0], vbh[1]);
                mma_f16(oacc[nt2 * 2],     pah[kc2], vbl[0], vbl[1]);
                mma_f16(oacc[nt2 * 2],     pal[kc2], vbh[0], vbh[1]);
                mma_f16(oacc[nt2 * 2 + 1], pah[kc2], vbh[2], vbh[3]);
                mma_f16(oacc[nt2 * 2 + 1], pah[kc2], vbl[2], vbl[3]);
                mma_f16(oacc[nt2 * 2 + 1], pal[kc2], vbh[2], vbh[3]);
            }
        }
    }

    float inv0 = 1.0f / lrow0, inv1 = 1.0f / lrow1;
    int r0 = qt * 128 + m0 + (lane >> 2);
    int r1 = r0 + 8;
#pragma unroll
    for (int nt = 0; nt < 8; nt++) {
        int col = h * HD + nt * 8 + (lane & 3) * 2;
        float2 v0 = make_float2(oacc[nt][0] * inv0, oacc[nt][1] * inv0);
        float2 v1 = make_float2(oacc[nt][2] * inv1, oacc[nt][3] * inv1);
        *(float2*)&out[((size_t)b * SEQ + r0) * HID + col] = v0;
        *(float2*)&out[((size_t)b * SEQ + r1) * HID + col] = v1;
    }
}

// ---------------- launch ----------------
extern "C" void kernel_launch(void* const* d_in, const int* in_sizes, int n_in,
                              void* d_out, int out_size) {
    const float* x      = (const float*)d_in[0];
    const float* norm_w = (const float*)d_in[1];
    const float* q_w    = (const float*)d_in[2];
    const float* q_g    = (const float*)d_in[3];
    const float* k_w    = (const float*)d_in[4];
    const float* k_g    = (const float*)d_in[5];
    const float* v_w    = (const float*)d_in[6];
    const float* v_g    = (const float*)d_in[7];
    const float* o_w    = (const float*)d_in[8];
    const float* o_g    = (const float*)d_in[9];
    float* out = (float*)d_out;

    void *p_xq_q, *p_xq_k, *p_xq_v, *p_xq_o;
    void *p_wq_q, *p_wq_k, *p_wq_v, *p_wq_o;
    void *p_gq, *p_gk, *p_gv, *p_go, *p_alpha;
    void *p_qb, *p_kb, *p_vb, *p_att;
    cudaGetSymbolAddress(&p_xq_q, g_xq_q);  cudaGetSymbolAddress(&p_xq_k, g_xq_k);
    cudaGetSymbolAddress(&p_xq_v, g_xq_v);  cudaGetSymbolAddress(&p_xq_o, g_xq_o);
    cudaGetSymbolAddress(&p_wq_q, g_wq_q);  cudaGetSymbolAddress(&p_wq_k, g_wq_k);
    cudaGetSymbolAddress(&p_wq_v, g_wq_v);  cudaGetSymbolAddress(&p_wq_o, g_wq_o);
    cudaGetSymbolAddress(&p_gq, g_gamma_q); cudaGetSymbolAddress(&p_gk, g_gamma_k);
    cudaGetSymbolAddress(&p_gv, g_gamma_v); cudaGetSymbolAddress(&p_go, g_gamma_o);
    cudaGetSymbolAddress(&p_alpha, g_alpha);
    cudaGetSymbolAddress(&p_qb, g_qb); cudaGetSymbolAddress(&p_kb, g_kb);
    cudaGetSymbolAddress(&p_vb, g_vb); cudaGetSymbolAddress(&p_att, g_att);

    // 1. weight scales + ternary quant
    alpha_all<<<4, 1024>>>(q_w, k_w, v_w, o_w);
    wquant_all<<<(2 * HID * HID + 2 * KVDIM * HID + 255) / 256, 256>>>(q_w, k_w, v_w, o_w);

    // 2. activation double-rmsnorm + int8 quant
    act_quant_qkv<<<T_TOKENS, 128>>>(x, norm_w, q_g, k_g, v_g);

    // 3. rope tables
    rope_tab<<<(SEQ * 32 + 255) / 256, 256>>>();

    // 4. QKV GEMMs (int8 tensor core, bit-exact)
    gemm_imma<<<dim3(128, 5), 256>>>((const int8_t*)p_xq_q, (const int8_t*)p_wq_q,
                                     (const float*)p_gq, (const float*)p_alpha + 0,
                                     (float*)p_qb, 0, NQH, nullptr);
    gemm_imma<<<dim3(128, 1), 256>>>((const int8_t*)p_xq_k, (const int8_t*)p_wq_k,
                                     (const float*)p_gk, (const float*)p_alpha + 1,
                                     (float*)p_kb, 0, NKVH, nullptr);
    gemm_imma<<<dim3(128, 1), 256>>>((const int8_t*)p_xq_v, (const int8_t*)p_wq_v,
                                     (const float*)p_gv, (const float*)p_alpha + 2,
                                     (float*)p_vb, 0, NKVH, nullptr);

    // 5. RoPE on q and k
    int qpairs = BATCH * NQH * SEQ * 32;
    int kpairs = BATCH * NKVH * SEQ * 32;
    rope_apply<<<(qpairs + 255) / 256, 256>>>((float*)p_qb, qpairs);
    rope_apply<<<(kpairs + 255) / 256, 256>>>((float*)p_kb, kpairs);

    // 6. attention (fp16 split mma flash)
    attn_mma<<<dim3(SEQ / 128, BATCH * NQH), 256>>>(
        (const float*)p_qb, (const float*)p_kb, (const float*)p_vb, (float*)p_att);

    // 7. O-proj quant + GEMM + residual
    act_quant_o<<<T_TOKENS, 128>>>(o_g);
    gemm_imma<<<dim3(128, 5), 256>>>((const int8_t*)p_xq_o, (const int8_t*)p_wq_o,
                                     (const float*)p_go, (const float*)p_alpha + 3,
                                     out, 1, 0, x);
}

// round 5
// speedup vs baseline: 2.1701x; 1.0603x over previous
#include <cuda_runtime.h>
#include <cuda_fp16.h>
#include <math.h>
#include <stdint.h>

#define T_TOKENS 16384
#define HID      640
#define NQH      10
#define NKVH     2
#define HD       64
#define SEQ      512
#define BATCH    32
#define KVDIM    128

// ---------------- scratch ----------------
__device__ __align__(16) int8_t g_xq_q[T_TOKENS * HID];
__device__ __align__(16) int8_t g_xq_k[T_TOKENS * HID];
__device__ __align__(16) int8_t g_xq_v[T_TOKENS * HID];
__device__ __align__(16) int8_t g_xq_o[T_TOKENS * HID];
__device__ __align__(16) int8_t g_wq_q[HID * HID];
__device__ __align__(16) int8_t g_wq_k[KVDIM * HID];
__device__ __align__(16) int8_t g_wq_v[KVDIM * HID];
__device__ __align__(16) int8_t g_wq_o[HID * HID];
__device__ float g_gamma_q[T_TOKENS];
__device__ float g_gamma_k[T_TOKENS];
__device__ float g_gamma_v[T_TOKENS];
__device__ float g_gamma_o[T_TOKENS];
__device__ float g_alpha[4];
__device__ float g_qb[BATCH * NQH * SEQ * HD];
__device__ float g_kb[BATCH * NKVH * SEQ * HD];
__device__ float g_vb[BATCH * NKVH * SEQ * HD];
__device__ float g_att[T_TOKENS * HID];
__device__ float g_cos[SEQ * 32];
__device__ float g_sin[SEQ * 32];

// ---------------- reduction helpers ----------------
__device__ __forceinline__ float warp_red(float v, int op) {
#pragma unroll
    for (int o = 16; o; o >>= 1) {
        float t = __shfl_xor_sync(0xffffffffu, v, o);
        v = op ? fmaxf(v, t) : v + t;
    }
    return v;
}
__device__ __forceinline__ float block_reduce(float v, int op, float* sm, int nwarps) {
    int lane = threadIdx.x & 31, w = threadIdx.x >> 5;
    v = warp_red(v, op);
    if (!lane) sm[w] = v;
    __syncthreads();
    if (w == 0) {
        v = (lane < nwarps) ? sm[lane] : (op ? -INFINITY : 0.0f);
        v = warp_red(v, op);
        if (!lane) sm[0] = v;
    }
    __syncthreads();
    v = sm[0];
    __syncthreads();
    return v;
}

// ---------------- weight alpha ----------------
__global__ void alpha_all(const float* __restrict__ qw, const float* __restrict__ kw,
                          const float* __restrict__ vw, const float* __restrict__ ow) {
    __shared__ float sm[32];
    int which = blockIdx.x;
    const float* w = which == 0 ? qw : which == 1 ? kw : which == 2 ? vw : ow;
    int n = (which == 1 || which == 2) ? (KVDIM * HID) : (HID * HID);
    float s = 0.0f;
    for (int i = threadIdx.x; i < n; i += 1024) s += fabsf(w[i]);
    s = block_reduce(s, 0, sm, 32);
    if (threadIdx.x == 0) g_alpha[which] = fmaxf(s / (float)n, 1e-10f);
}

// ---------------- weight ternary quant ----------------
__global__ void wquant_all(const float* __restrict__ qw, const float* __restrict__ kw,
                           const float* __restrict__ vw, const float* __restrict__ ow) {
    int idx = blockIdx.x * blockDim.x + threadIdx.x;
    const float* w; int8_t* dst; int off; int which;
    const int nQ = HID * HID, nK = KVDIM * HID;
    if (idx < nQ)                       { which = 0; w = qw; dst = g_wq_q; off = idx; }
    else if (idx < nQ + nK)             { which = 1; w = kw; dst = g_wq_k; off = idx - nQ; }
    else if (idx < nQ + 2 * nK)         { which = 2; w = vw; dst = g_wq_v; off = idx - nQ - nK; }
    else if (idx < 2 * nQ + 2 * nK)     { which = 3; w = ow; dst = g_wq_o; off = idx - nQ - 2 * nK; }
    else return;
    float a = g_alpha[which];
    float q = rintf(w[off] / a);
    q = fminf(fmaxf(q, -1.0f), 1.0f);
    dst[off] = (int8_t)q;
}

// ---------------- activation quant, warp-per-token (QKV) ----------------
__global__ __launch_bounds__(256) void act_quant_qkv(
    const float* __restrict__ x, const float* __restrict__ nw,
    const float* __restrict__ qg, const float* __restrict__ kg, const float* __restrict__ vg) {
    int warp = threadIdx.x >> 5, lane = threadIdx.x & 31;
    int t = blockIdx.x * 8 + warp;
    const float4* xr = (const float4*)(x + (size_t)t * HID);
    const float4* nw4 = (const float4*)nw;
    float4 v[5], h[5];
    float ss = 0.0f;
#pragma unroll
    for (int j = 0; j < 5; j++) {
        v[j] = xr[lane + j * 32];
        ss += v[j].x * v[j].x + v[j].y * v[j].y + v[j].z * v[j].z + v[j].w * v[j].w;
    }
    ss = warp_red(ss, 0);
    float rinv = rsqrtf(ss / (float)HID + 1e-6f);
    float s2 = 0.0f;
#pragma unroll
    for (int j = 0; j < 5; j++) {
        float4 g4 = nw4[lane + j * 32];
        h[j].x = v[j].x * rinv * g4.x; h[j].y = v[j].y * rinv * g4.y;
        h[j].z = v[j].z * rinv * g4.z; h[j].w = v[j].w * rinv * g4.w;
        s2 += h[j].x * h[j].x + h[j].y * h[j].y + h[j].z * h[j].z + h[j].w * h[j].w;
    }
    s2 = warp_red(s2, 0);
    float rinv2 = rsqrtf(s2 / (float)HID + 1e-6f);

    const float* gains[3] = { qg, kg, vg };
    int8_t* dsts[3] = { g_xq_q, g_xq_k, g_xq_v };
    float* gmas[3] = { g_gamma_q, g_gamma_k, g_gamma_v };
#pragma unroll
    for (int which = 0; which < 3; which++) {
        const float4* g4p = (const float4*)gains[which];
        float4 hq[5];
        float gm = 0.0f;
#pragma unroll
        for (int j = 0; j < 5; j++) {
            float4 g4 = g4p[lane + j * 32];
            hq[j].x = h[j].x * rinv2 * g4.x; hq[j].y = h[j].y * rinv2 * g4.y;
            hq[j].z = h[j].z * rinv2 * g4.z; hq[j].w = h[j].w * rinv2 * g4.w;
            gm = fmaxf(gm, fmaxf(fmaxf(fabsf(hq[j].x), fabsf(hq[j].y)),
                                 fmaxf(fabsf(hq[j].z), fabsf(hq[j].w))));
        }
        gm = warp_red(gm, 1);
        gm = fmaxf(gm, 1e-10f);
        float sc = 127.0f / gm;
        char4* dst4 = (char4*)(dsts[which] + (size_t)t * HID);
#pragma unroll
        for (int j = 0; j < 5; j++) {
            char4 q;
            q.x = (int8_t)fminf(fmaxf(rintf(hq[j].x * sc), -128.0f), 127.0f);
            q.y = (int8_t)fminf(fmaxf(rintf(hq[j].y * sc), -128.0f), 127.0f);
            q.z = (int8_t)fminf(fmaxf(rintf(hq[j].z * sc), -128.0f), 127.0f);
            q.w = (int8_t)fminf(fmaxf(rintf(hq[j].w * sc), -128.0f), 127.0f);
            dst4[lane + j * 32] = q;
        }
        if (lane == 0) gmas[which][t] = gm;
    }
}

// ---------------- activation quant, warp-per-token (O path) ----------------
__global__ __launch_bounds__(256) void act_quant_o(const float* __restrict__ og) {
    int warp = threadIdx.x >> 5, lane = threadIdx.x & 31;
    int t = blockIdx.x * 8 + warp;
    const float4* xr = (const float4*)(g_att + (size_t)t * HID);
    const float4* og4 = (const float4*)og;
    float4 v[5], hq[5];
    float ss = 0.0f;
#pragma unroll
    for (int j = 0; j < 5; j++) {
        v[j] = xr[lane + j * 32];
        ss += v[j].x * v[j].x + v[j].y * v[j].y + v[j].z * v[j].z + v[j].w * v[j].w;
    }
    ss = warp_red(ss, 0);
    float rinv = rsqrtf(ss / (float)HID + 1e-6f);
    float gm = 0.0f;
#pragma unroll
    for (int j = 0; j < 5; j++) {
        float4 g4 = og4[lane + j * 32];
        hq[j].x = v[j].x * rinv * g4.x; hq[j].y = v[j].y * rinv * g4.y;
        hq[j].z = v[j].z * rinv * g4.z; hq[j].w = v[j].w * rinv * g4.w;
        gm = fmaxf(gm, fmaxf(fmaxf(fabsf(hq[j].x), fabsf(hq[j].y)),
                             fmaxf(fabsf(hq[j].z), fabsf(hq[j].w))));
    }
    gm = warp_red(gm, 1);
    gm = fmaxf(gm, 1e-10f);
    float sc = 127.0f / gm;
    char4* dst4 = (char4*)(g_xq_o + (size_t)t * HID);
#pragma unroll
    for (int j = 0; j < 5; j++) {
        char4 q;
        q.x = (int8_t)fminf(fmaxf(rintf(hq[j].x * sc), -128.0f), 127.0f);
        q.y = (int8_t)fminf(fmaxf(rintf(hq[j].y * sc), -128.0f), 127.0f);
        q.z = (int8_t)fminf(fmaxf(rintf(hq[j].z * sc), -128.0f), 127.0f);
        q.w = (int8_t)fminf(fmaxf(rintf(hq[j].w * sc), -128.0f), 127.0f);
        dst4[lane + j * 32] = q;
    }
    if (lane == 0) g_gamma_o[t] = gm;
}

// ---------------- mma / async helpers ----------------
__device__ __forceinline__ uint32_t smem_u32(const void* p) {
    return (uint32_t)__cvta_generic_to_shared(p);
}
__device__ __forceinline__ void ldmx4(uint32_t* r, uint32_t addr) {
    asm volatile("ldmatrix.sync.aligned.m8n8.x4.shared.b16 {%0,%1,%2,%3}, [%4];\n"
                 : "=r"(r[0]), "=r"(r[1]), "=r"(r[2]), "=r"(r[3]) : "r"(addr));
}
__device__ __forceinline__ void ldmx4t(uint32_t* r, uint32_t addr) {
    asm volatile("ldmatrix.sync.aligned.m8n8.x4.trans.shared.b16 {%0,%1,%2,%3}, [%4];\n"
                 : "=r"(r[0]), "=r"(r[1]), "=r"(r[2]), "=r"(r[3]) : "r"(addr));
}
__device__ __forceinline__ void mma_f16(float* c, const uint32_t* a, uint32_t b0, uint32_t b1) {
    asm volatile("mma.sync.aligned.m16n8k16.row.col.f32.f16.f16.f32 "
                 "{%0,%1,%2,%3}, {%4,%5,%6,%7}, {%8,%9}, {%0,%1,%2,%3};\n"
                 : "+f"(c[0]), "+f"(c[1]), "+f"(c[2]), "+f"(c[3])
                 : "r"(a[0]), "r"(a[1]), "r"(a[2]), "r"(a[3]), "r"(b0), "r"(b1));
}
__device__ __forceinline__ void mma_s8(int* c, const uint32_t* a, uint32_t b0, uint32_t b1) {
    asm volatile("mma.sync.aligned.m16n8k32.row.col.s32.s8.s8.s32 "
                 "{%0,%1,%2,%3}, {%4,%5,%6,%7}, {%8,%9}, {%0,%1,%2,%3};\n"
                 : "+r"(c[0]), "+r"(c[1]), "+r"(c[2]), "+r"(c[3])
                 : "r"(a[0]), "r"(a[1]), "r"(a[2]), "r"(a[3]), "r"(b0), "r"(b1));
}
__device__ __forceinline__ void cp16(void* s, const void* g) {
    asm volatile("cp.async.cg.shared.global [%0], [%1], 16;\n"
                 :: "r"(smem_u32(s)), "l"(g));
}
__device__ __forceinline__ void cp_commit() {
    asm volatile("cp.async.commit_group;\n");
}
template <int N>
__device__ __forceinline__ void cp_wait() {
    asm volatile("cp.async.wait_group %0;\n" :: "n"(N));
}
__device__ __forceinline__ uint32_t pack_h2(__half x, __half y) {
    __half2 h = __halves2half2(x, y);
    return *(uint32_t*)&h;
}
__device__ __forceinline__ void split_h(float x, __half& hi, __half& lo) {
    hi = __float2half_rn(x);
    lo = __float2half_rn(x - __half2float(hi));
}

// ---------------- int8 tensor-core GEMM, cp.async double-buffered -------------
// 128x128 tile, 8 warps 4x2, warp tile 32x64; rope optionally fused in epilogue.
#define GP 144
#define GSTAGE (128 * GP)
__global__ __launch_bounds__(256) void gemm_imma(
    const int8_t* __restrict__ A, const int8_t* __restrict__ Bw,
    const float* __restrict__ gamma, const float* __restrict__ alpha_p,
    float* __restrict__ out, int mode, int nheads, const float* __restrict__ resid,
    int rope) {
    extern __shared__ int8_t dsm[];
    int8_t* As = dsm;                 // 2 stages
    int8_t* Bs = dsm + 2 * GSTAGE;    // 2 stages
    int t0 = blockIdx.x * 128;
    int n0 = blockIdx.y * 128;
    int tid = threadIdx.x, warp = tid >> 5, lane = tid & 31;
    int wm = warp >> 1, wn = warp & 1;

    int acc[2][8][4];
#pragma unroll
    for (int mt = 0; mt < 2; mt++)
#pragma unroll
        for (int nt = 0; nt < 8; nt++)
#pragma unroll
            for (int i = 0; i < 4; i++) acc[mt][nt][i] = 0;

    int row = tid >> 1;                // 2 threads per row, each 4 segs
    int sh = (tid & 1) * 4;
#pragma unroll
    for (int c = 0; c <= 5; c++) {
        if (c < 5) {                   // prefetch chunk c into stage c&1
            int st = (c & 1) * GSTAGE;
#pragma unroll
            for (int s = 0; s < 4; s++) {
                int seg = sh + s;
                cp16(&As[st + row * GP + seg * 16],
                     &A[(size_t)(t0 + row) * HID + c * 128 + seg * 16]);
                cp16(&Bs[st + row * GP + seg * 16],
                     &Bw[(size_t)(n0 + row) * HID + c * 128 + seg * 16]);
            }
            cp_commit();
        }
        if (c == 0) continue;          // nothing to compute yet
        int cc = c - 1;                // compute chunk cc
        if (c < 5) cp_wait<1>(); else cp_wait<0>();
        __syncthreads();
        int st = (cc & 1) * GSTAGE;
#pragma unroll
        for (int ks = 0; ks < 4; ks++) {
            uint32_t af[2][4];
#pragma unroll
            for (int mt = 0; mt < 2; mt++)
                ldmx4(af[mt], smem_u32(&As[st + (wm * 32 + mt * 16 + (lane & 15)) * GP +
                                            ks * 32 + (lane >> 4) * 16]));
#pragma unroll
            for (int np = 0; np < 4; np++) {
                uint32_t bf[4];
                ldmx4(bf, smem_u32(&Bs[st + (wn * 64 + np * 16 + (lane & 15)) * GP +
                                        ks * 32 + (lane >> 4) * 16]));
#pragma unroll
                for (int mt = 0; mt < 2; mt++) {
                    mma_s8(acc[mt][np * 2],     af[mt], bf[0], bf[2]);
                    mma_s8(acc[mt][np * 2 + 1], af[mt], bf[1], bf[3]);
                }
            }
        }
        __syncthreads();
    }

    float alpha = *alpha_p * (1.0f / 127.0f);
#pragma unroll
    for (int mt = 0; mt < 2; mt++) {
        int r0 = t0 + wm * 32 + mt * 16 + (lane >> 2);
        int r1 = r0 + 8;
        float s0 = alpha * gamma[r0];
        float s1 = alpha * gamma[r1];
#pragma unroll
        for (int nt = 0; nt < 8; nt++) {
            int n = n0 + wn * 64 + nt * 8 + (lane & 3) * 2;
            float v00 = (float)acc[mt][nt][0] * s0, v01 = (float)acc[mt][nt][1] * s0;
            float v10 = (float)acc[mt][nt][2] * s1, v11 = (float)acc[mt][nt][3] * s1;
            if (mode == 0) {
                int head = n >> 6, d = n & 63;
                int b0i = r0 >> 9, l0 = r0 & 511;
                int b1i = r1 >> 9, l1 = r1 & 511;
                if (rope) {
                    int p = d >> 1;
                    float c0 = g_cos[l0 * 32 + p], sn0 = g_sin[l0 * 32 + p];
                    float c1 = g_cos[l1 * 32 + p], sn1 = g_sin[l1 * 32 + p];
                    float t00 = v00 * c0 - v01 * sn0, t01 = v01 * c0 + v00 * sn0;
                    float t10 = v10 * c1 - v11 * sn1, t11 = v11 * c1 + v10 * sn1;
                    v00 = t00; v01 = t01; v10 = t10; v11 = t11;
                }
                *(float2*)&out[(((size_t)b0i * nheads + head) * SEQ + l0) * HD + d] =
                    make_float2(v00, v01);
                *(float2*)&out[(((size_t)b1i * nheads + head) * SEQ + l1) * HD + d] =
                    make_float2(v10, v11);
            } else {
                const float* rr0 = resid + (size_t)r0 * HID + n;
                const float* rr1 = resid + (size_t)r1 * HID + n;
                *(float2*)&out[(size_t)r0 * HID + n] = make_float2(v00 + rr0[0], v01 + rr0[1]);
                *(float2*)&out[(size_t)r1 * HID + n] = make_float2(v10 + rr1[0], v11 + rr1[1]);
            }
        }
    }
}

// ---------------- RoPE tables ----------------
__global__ void rope_tab() {
    int idx = blockIdx.x * blockDim.x + threadIdx.x;
    if (idx >= SEQ * 32) return;
    int l = idx >> 5, p = idx & 31;
    double freq = pow(500000.0, -(double)p / 32.0);
    double a = (double)l * freq;
    g_cos[idx] = (float)cos(a);
    g_sin[idx] = (float)sin(a);
}

// ---------------- attention: flash, fp16 split mma (fp32-accurate) --------------
#define SPITCH 72
__global__ __launch_bounds__(256) void attn_mma(
    const float* __restrict__ q, const float* __restrict__ k,
    const float* __restrict__ v, float* __restrict__ out) {
    __shared__ __align__(16) __half SB[18432];

    int tid = threadIdx.x;
    int warp = tid >> 5, lane = tid & 31;
    int qt = blockIdx.x;
    int bh = blockIdx.y;
    int b = bh / NQH, h = bh % NQH;
    int kvh = h / (NQH / NKVH);

    const float* qb = q + (((size_t)(b * NQH + h) * SEQ) + qt * 128) * HD;
    const float* kb = k + ((size_t)(b * NKVH + kvh) * SEQ) * HD;
    const float* vb = v + ((size_t)(b * NKVH + kvh) * SEQ) * HD;

    __half* Qh = SB;
    __half* Ql = SB + 9216;

#pragma unroll
    for (int it = 0; it < 8; it++) {
        int f4 = tid + it * 256;
        int e = f4 * 4;
        int row = e >> 6, col = e & 63;
        float4 qv = *(const float4*)(qb + e);
        __half h0, l0, h1, l1, h2, l2, h3, l3;
        split_h(qv.x * 0.125f, h0, l0); split_h(qv.y * 0.125f, h1, l1);
        split_h(qv.z * 0.125f, h2, l2); split_h(qv.w * 0.125f, h3, l3);
        *(uint32_t*)&Qh[row * SPITCH + col]     = pack_h2(h0, h1);
        *(uint32_t*)&Qh[row * SPITCH + col + 2] = pack_h2(h2, h3);
        *(uint32_t*)&Ql[row * SPITCH + col]     = pack_h2(l0, l1);
        *(uint32_t*)&Ql[row * SPITCH + col + 2] = pack_h2(l2, l3);
    }
    __syncthreads();

    uint32_t qah[4][4], qal[4][4];
    int m0 = warp * 16;
#pragma unroll
    for (int kc = 0; kc < 4; kc++) {
        int r = m0 + (lane & 15), c = kc * 16 + (lane >> 4) * 8;
        ldmx4(qah[kc], smem_u32(&Qh[r * SPITCH + c]));
        ldmx4(qal[kc], smem_u32(&Ql[r * SPITCH + c]));
    }
    __syncthreads();

    __half* Kh = SB;
    __half* Kl = SB + 4608;
    __half* Vh = SB + 9216;
    __half* Vl = SB + 13824;

    float oacc[8][4];
#pragma unroll
    for (int nt = 0; nt < 8; nt++)
#pragma unroll
        for (int i = 0; i < 4; i++) oacc[nt][i] = 0.0f;
    float mrow0 = -1e30f, mrow1 = -1e30f, lrow0 = 0.0f, lrow1 = 0.0f;

    for (int kt = 0; kt < 8; kt++) {
        if (kt) __syncthreads();
        const float* kbt = kb + (size_t)kt * 64 * HD;
        const float* vbt = vb + (size_t)kt * 64 * HD;
#pragma unroll
        for (int it = 0; it < 4; it++) {
            int f4 = tid + it * 256;
            int e = f4 * 4;
            int row = e >> 6, col = e & 63;
            {
                float4 x4 = *(const float4*)(kbt + e);
                __half h0, l0, h1, l1, h2, l2, h3, l3;
                split_h(x4.x, h0, l0); split_h(x4.y, h1, l1);
                split_h(x4.z, h2, l2); split_h(x4.w, h3, l3);
                *(uint32_t*)&Kh[row * SPITCH + col]     = pack_h2(h0, h1);
                *(uint32_t*)&Kh[row * SPITCH + col + 2] = pack_h2(h2, h3);
                *(uint32_t*)&Kl[row * SPITCH + col]     = pack_h2(l0, l1);
                *(uint32_t*)&Kl[row * SPITCH + col + 2] = pack_h2(l2, l3);
            }
            {
                float4 x4 = *(const float4*)(vbt + e);
                __half h0, l0, h1, l1, h2, l2, h3, l3;
                split_h(x4.x, h0, l0); split_h(x4.y, h1, l1);
                split_h(x4.z, h2, l2); split_h(x4.w, h3, l3);
                *(uint32_t*)&Vh[row * SPITCH + col]     = pack_h2(h0, h1);
                *(uint32_t*)&Vh[row * SPITCH + col + 2] = pack_h2(h2, h3);
                *(uint32_t*)&Vl[row * SPITCH + col]     = pack_h2(l0, l1);
                *(uint32_t*)&Vl[row * SPITCH + col + 2] = pack_h2(l2, l3);
            }
        }
        __syncthreads();

        float sacc[8][4];
#pragma unroll
        for (int nt = 0; nt < 8; nt++)
#pragma unroll
            for (int i = 0; i < 4; i++) sacc[nt][i] = 0.0f;
        int g = lane >> 3;
        int n_off = (g >= 2) ? 8 : 0, k_off = (g & 1) * 8;
#pragma unroll
        for (int nt2 = 0; nt2 < 4; nt2++) {
#pragma unroll
            for (int kc = 0; kc < 4; kc++) {
                uint32_t kbh[4], kbl[4];
                int r = nt2 * 16 + n_off + (lane & 7), c = kc * 16 + k_off;
                ldmx4(kbh, smem_u32(&Kh[r * SPITCH + c]));
                ldmx4(kbl, smem_u32(&Kl[r * SPITCH + c]));
                mma_f16(sacc[nt2 * 2],     qah[kc], kbh[0], kbh[1]);
                mma_f16(sacc[nt2 * 2],     qah[kc], kbl[0], kbl[1]);
                mma_f16(sacc[nt2 * 2],     qal[kc], kbh[0], kbh[1]);
                mma_f16(sacc[nt2 * 2 + 1], qah[kc], kbh[2], kbh[3]);
                mma_f16(sacc[nt2 * 2 + 1], qah[kc], kbl[2], kbl[3]);
                mma_f16(sacc[nt2 * 2 + 1], qal[kc], kbh[2], kbh[3]);
            }
        }

        float mx0 = -1e30f, mx1 = -1e30f;
#pragma unroll
        for (int nt = 0; nt < 8; nt++) {
            mx0 = fmaxf(mx0, fmaxf(sacc[nt][0], sacc[nt][1]));
            mx1 = fmaxf(mx1, fmaxf(sacc[nt][2], sacc[nt][3]));
        }
        mx0 = fmaxf(mx0, __shfl_xor_sync(0xffffffffu, mx0, 1));
        mx0 = fmaxf(mx0, __shfl_xor_sync(0xffffffffu, mx0, 2));
        mx1 = fmaxf(mx1, __shfl_xor_sync(0xffffffffu, mx1, 1));
        mx1 = fmaxf(mx1, __shfl_xor_sync(0xffffffffu, mx1, 2));
        float mn0 = fmaxf(mrow0, mx0), mn1 = fmaxf(mrow1, mx1);
        float e0 = __expf(mrow0 - mn0), e1 = __expf(mrow1 - mn1);
        mrow0 = mn0; mrow1 = mn1;

        float sum0 = 0.0f, sum1 = 0.0f;
        uint32_t pah[4][4], pal[4][4];
#pragma unroll
        for (int kc2 = 0; kc2 < 4; kc2++) {
            int nta = kc2 * 2, ntb = nta + 1;
            float p[8];
            p[0] = __expf(sacc[nta][0] - mn0); p[1] = __expf(sacc[nta][1] - mn0);
            p[2] = __expf(sacc[nta][2] - mn1); p[3] = __expf(sacc[nta][3] - mn1);
            p[4] = __expf(sacc[ntb][0] - mn0); p[5] = __expf(sacc[ntb][1] - mn0);
            p[6] = __expf(sacc[ntb][2] - mn1); p[7] = __expf(sacc[ntb][3] - mn1);
            __half ph[8], pl[8];
#pragma unroll
            for (int i = 0; i < 8; i++) split_h(p[i], ph[i], pl[i]);
            sum0 += p[0] + p[1] + p[4] + p[5];
            sum1 += p[2] + p[3] + p[6] + p[7];
            pah[kc2][0] = pack_h2(ph[0], ph[1]); pal[kc2][0] = pack_h2(pl[0], pl[1]);
            pah[kc2][1] = pack_h2(ph[2], ph[3]); pal[kc2][1] = pack_h2(pl[2], pl[3]);
            pah[kc2][2] = pack_h2(ph[4], ph[5]); pal[kc2][2] = pack_h2(pl[4], pl[5]);
            pah[kc2][3] = pack_h2(ph[6], ph[7]); pal[kc2][3] = pack_h2(pl[6], pl[7]);
        }
        sum0 += __shfl_xor_sync(0xffffffffu, sum0, 1);
        sum0 += __shfl_xor_sync(0xffffffffu, sum0, 2);
        sum1 += __shfl_xor_sync(0xffffffffu, sum1, 1);
        sum1 += __shfl_xor_sync(0xffffffffu, sum1, 2);
        lrow0 = lrow0 * e0 + sum0;
        lrow1 = lrow1 * e1 + sum1;

#pragma unroll
        for (int nt = 0; nt < 8; nt++) {
            oacc[nt][0] *= e0; oacc[nt][1] *= e0;
            oacc[nt][2] *= e1; oacc[nt][3] *= e1;
        }

#pragma unroll
        for (int kc2 = 0; kc2 < 4; kc2++) {
#pragma unroll
            for (int nt2 = 0; nt2 < 4; nt2++) {
                uint32_t vbh[4], vbl[4];
                int r = kc2 * 16 + (g & 1) * 8 + (lane & 7);
                int c = nt2 * 16 + ((g >= 2) ? 8 : 0);
                ldmx4t(vbh, smem_u32(&Vh[r * SPITCH + c]));
                ldmx4t(vbl, smem_u32(&Vl[r * SPITCH + c]));
                mma_f16(oacc[nt2 * 2],     pah[kc2], vbh[0], vbh[1]);
                mma_f16(oacc[nt2 * 2],     pah[kc2], vbl[0], vbl[1]);
                mma_f16(oacc[nt2 * 2],     pal[kc2], vbh[0], vbh[1]);
                mma_f16(oacc[nt2 * 2 + 1], pah[kc2], vbh[2], vbh[3]);
                mma_f16(oacc[nt2 * 2 + 1], pah[kc2], vbl[2], vbl[3]);
                mma_f16(oacc[nt2 * 2 + 1], pal[kc2], vbh[2], vbh[3]);
            }
        }
    }

    float inv0 = 1.0f / lrow0, inv1 = 1.0f / lrow1;
    int r0 = qt * 128 + m0 + (lane >> 2);
    int r1 = r0 + 8;
#pragma unroll
    for (int nt = 0; nt < 8; nt++) {
        int col = h * HD + nt * 8 + (lane & 3) * 2;
        float2 v0 = make_float2(oacc[nt][0] * inv0, oacc[nt][1] * inv0);
        float2 v1 = make_float2(oacc[nt][2] * inv1, oacc[nt][3] * inv1);
        *(float2*)&out[((size_t)b * SEQ + r0) * HID + col] = v0;
        *(float2*)&out[((size_t)b * SEQ + r1) * HID + col] = v1;
    }
}

// ---------------- launch ----------------
extern "C" void kernel_launch(void* const* d_in, const int* in_sizes, int n_in,
                              void* d_out, int out_size) {
    const float* x      = (const float*)d_in[0];
    const float* norm_w = (const float*)d_in[1];
    const float* q_w    = (const float*)d_in[2];
    const float* q_g    = (const float*)d_in[3];
    const float* k_w    = (const float*)d_in[4];
    const float* k_g    = (const float*)d_in[5];
    const float* v_w    = (const float*)d_in[6];
    const float* v_g    = (const float*)d_in[7];
    const float* o_w    = (const float*)d_in[8];
    const float* o_g    = (const float*)d_in[9];
    float* out = (float*)d_out;

    void *p_xq_q, *p_xq_k, *p_xq_v, *p_xq_o;
    void *p_wq_q, *p_wq_k, *p_wq_v, *p_wq_o;
    void *p_gq, *p_gk, *p_gv, *p_go, *p_alpha;
    void *p_qb, *p_kb, *p_vb, *p_att;
    cudaGetSymbolAddress(&p_xq_q, g_xq_q);  cudaGetSymbolAddress(&p_xq_k, g_xq_k);
    cudaGetSymbolAddress(&p_xq_v, g_xq_v);  cudaGetSymbolAddress(&p_xq_o, g_xq_o);
    cudaGetSymbolAddress(&p_wq_q, g_wq_q);  cudaGetSymbolAddress(&p_wq_k, g_wq_k);
    cudaGetSymbolAddress(&p_wq_v, g_wq_v);  cudaGetSymbolAddress(&p_wq_o, g_wq_o);
    cudaGetSymbolAddress(&p_gq, g_gamma_q); cudaGetSymbolAddress(&p_gk, g_gamma_k);
    cudaGetSymbolAddress(&p_gv, g_gamma_v); cudaGetSymbolAddress(&p_go, g_gamma_o);
    cudaGetSymbolAddress(&p_alpha, g_alpha);
    cudaGetSymbolAddress(&p_qb, g_qb); cudaGetSymbolAddress(&p_kb, g_kb);
    cudaGetSymbolAddress(&p_vb, g_vb); cudaGetSymbolAddress(&p_att, g_att);

    const int GEMM_SMEM = 4 * GSTAGE;   // 73728 B
    cudaFuncSetAttribute(gemm_imma, cudaFuncAttributeMaxDynamicSharedMemorySize, GEMM_SMEM);

    // 1. rope tables (independent; run first)
    rope_tab<<<(SEQ * 32 + 255) / 256, 256>>>();

    // 2. weight scales + ternary quant
    alpha_all<<<4, 1024>>>(q_w, k_w, v_w, o_w);
    wquant_all<<<(2 * HID * HID + 2 * KVDIM * HID + 255) / 256, 256>>>(q_w, k_w, v_w, o_w);

    // 3. activation double-rmsnorm + int8 quant (warp per token)
    act_quant_qkv<<<T_TOKENS / 8, 256>>>(x, norm_w, q_g, k_g, v_g);

    // 4. QKV GEMMs (int8 TC, cp.async pipelined; RoPE fused for Q,K)
    gemm_imma<<<dim3(128, 5), 256, GEMM_SMEM>>>((const int8_t*)p_xq_q, (const int8_t*)p_wq_q,
                                     (const float*)p_gq, (const float*)p_alpha + 0,
                                     (float*)p_qb, 0, NQH, nullptr, 1);
    gemm_imma<<<dim3(128, 1), 256, GEMM_SMEM>>>((const int8_t*)p_xq_k, (const int8_t*)p_wq_k,
                                     (const float*)p_gk, (const float*)p_alpha + 1,
                                     (float*)p_kb, 0, NKVH, nullptr, 1);
    gemm_imma<<<dim3(128, 1), 256, GEMM_SMEM>>>((const int8_t*)p_xq_v, (const int8_t*)p_wq_v,
                                     (const float*)p_gv, (const float*)p_alpha + 2,
                                     (float*)p_vb, 0, NKVH, nullptr, 0);

    // 5. attention (fp16 split mma flash)
    attn_mma<<<dim3(SEQ / 128, BATCH * NQH), 256>>>(
        (const float*)p_qb, (const float*)p_kb, (const float*)p_vb, (float*)p_att);

    // 6. O-proj quant + GEMM + residual
    act_quant_o<<<T_TOKENS / 8, 256>>>(o_g);
    gemm_imma<<<dim3(128, 5), 256, GEMM_SMEM>>>((const int8_t*)p_xq_o, (const int8_t*)p_wq_o,
                                     (const float*)p_go, (const float*)p_alpha + 3,
                                     out, 1, 0, x, 0);
}

// round 7
// speedup vs baseline: 2.2546x; 1.0389x over previous
#include <cuda_runtime.h>
#include <cuda_fp16.h>
#include <math.h>
#include <stdint.h>

#define T_TOKENS 16384
#define HID      640
#define NQH      10
#define NKVH     2
#define HD       64
#define SEQ      512
#define BATCH    32
#define KVDIM    128

// ---------------- scratch ----------------
__device__ __align__(16) int8_t g_xq_q[T_TOKENS * HID];
__device__ __align__(16) int8_t g_xq_k[T_TOKENS * HID];
__device__ __align__(16) int8_t g_xq_v[T_TOKENS * HID];
__device__ __align__(16) int8_t g_xq_o[T_TOKENS * HID];
__device__ __align__(16) int8_t g_wq_q[HID * HID];
__device__ __align__(16) int8_t g_wq_k[KVDIM * HID];
__device__ __align__(16) int8_t g_wq_v[KVDIM * HID];
__device__ __align__(16) int8_t g_wq_o[HID * HID];
__device__ float g_gamma_q[T_TOKENS];
__device__ float g_gamma_k[T_TOKENS];
__device__ float g_gamma_v[T_TOKENS];
__device__ float g_gamma_o[T_TOKENS];
__device__ float g_alpha[4];
__device__ __align__(16) __half g_qh[BATCH * NQH * SEQ * HD];
__device__ __align__(16) __half g_ql[BATCH * NQH * SEQ * HD];
__device__ __align__(16) __half g_kh[BATCH * NKVH * SEQ * HD];
__device__ __align__(16) __half g_kl[BATCH * NKVH * SEQ * HD];
__device__ __align__(16) __half g_vh[BATCH * NKVH * SEQ * HD];
__device__ __align__(16) __half g_vl[BATCH * NKVH * SEQ * HD];
__device__ float g_att[T_TOKENS * HID];
__device__ float g_cos[SEQ * 32];
__device__ float g_sin[SEQ * 32];

// ---------------- reduction helpers ----------------
__device__ __forceinline__ float warp_red(float v, int op) {
#pragma unroll
    for (int o = 16; o; o >>= 1) {
        float t = __shfl_xor_sync(0xffffffffu, v, o);
        v = op ? fmaxf(v, t) : v + t;
    }
    return v;
}
__device__ __forceinline__ float block_reduce(float v, int op, float* sm, int nwarps) {
    int lane = threadIdx.x & 31, w = threadIdx.x >> 5;
    v = warp_red(v, op);
    if (!lane) sm[w] = v;
    __syncthreads();
    if (w == 0) {
        v = (lane < nwarps) ? sm[lane] : (op ? -INFINITY : 0.0f);
        v = warp_red(v, op);
        if (!lane) sm[0] = v;
    }
    __syncthreads();
    v = sm[0];
    __syncthreads();
    return v;
}

// ---------------- weight alpha ----------------
__global__ void alpha_all(const float* __restrict__ qw, const float* __restrict__ kw,
                          const float* __restrict__ vw, const float* __restrict__ ow) {
    __shared__ float sm[32];
    int which = blockIdx.x;
    const float* w = which == 0 ? qw : which == 1 ? kw : which == 2 ? vw : ow;
    int n = (which == 1 || which == 2) ? (KVDIM * HID) : (HID * HID);
    float s = 0.0f;
    for (int i = threadIdx.x; i < n; i += 1024) s += fabsf(w[i]);
    s = block_reduce(s, 0, sm, 32);
    if (threadIdx.x == 0) g_alpha[which] = fmaxf(s / (float)n, 1e-10f);
}

// ---------------- weight ternary quant ----------------
__global__ void wquant_all(const float* __restrict__ qw, const float* __restrict__ kw,
                           const float* __restrict__ vw, const float* __restrict__ ow) {
    int idx = blockIdx.x * blockDim.x + threadIdx.x;
    const float* w; int8_t* dst; int off; int which;
    const int nQ = HID * HID, nK = KVDIM * HID;
    if (idx < nQ)                       { which = 0; w = qw; dst = g_wq_q; off = idx; }
    else if (idx < nQ + nK)             { which = 1; w = kw; dst = g_wq_k; off = idx - nQ; }
    else if (idx < nQ + 2 * nK)         { which = 2; w = vw; dst = g_wq_v; off = idx - nQ - nK; }
    else if (idx < 2 * nQ + 2 * nK)     { which = 3; w = ow; dst = g_wq_o; off = idx - nQ - 2 * nK; }
    else return;
    float a = g_alpha[which];
    float q = rintf(w[off] / a);
    q = fminf(fmaxf(q, -1.0f), 1.0f);
    dst[off] = (int8_t)q;
}

// ---------------- activation quant, warp-per-token (QKV) ----------------
__global__ __launch_bounds__(256) void act_quant_qkv(
    const float* __restrict__ x, const float* __restrict__ nw,
    const float* __restrict__ qg, const float* __restrict__ kg, const float* __restrict__ vg) {
    int warp = threadIdx.x >> 5, lane = threadIdx.x & 31;
    int t = blockIdx.x * 8 + warp;
    const float4* xr = (const float4*)(x + (size_t)t * HID);
    const float4* nw4 = (const float4*)nw;
    float4 v[5], h[5];
    float ss = 0.0f;
#pragma unroll
    for (int j = 0; j < 5; j++) {
        v[j] = xr[lane + j * 32];
        ss += v[j].x * v[j].x + v[j].y * v[j].y + v[j].z * v[j].z + v[j].w * v[j].w;
    }
    ss = warp_red(ss, 0);
    float rinv = rsqrtf(ss / (float)HID + 1e-6f);
    float s2 = 0.0f;
#pragma unroll
    for (int j = 0; j < 5; j++) {
        float4 g4 = nw4[lane + j * 32];
        h[j].x = v[j].x * rinv * g4.x; h[j].y = v[j].y * rinv * g4.y;
        h[j].z = v[j].z * rinv * g4.z; h[j].w = v[j].w * rinv * g4.w;
        s2 += h[j].x * h[j].x + h[j].y * h[j].y + h[j].z * h[j].z + h[j].w * h[j].w;
    }
    s2 = warp_red(s2, 0);
    float rinv2 = rsqrtf(s2 / (float)HID + 1e-6f);

    const float* gains[3] = { qg, kg, vg };
    int8_t* dsts[3] = { g_xq_q, g_xq_k, g_xq_v };
    float* gmas[3] = { g_gamma_q, g_gamma_k, g_gamma_v };
#pragma unroll
    for (int which = 0; which < 3; which++) {
        const float4* g4p = (const float4*)gains[which];
        float4 hq[5];
        float gm = 0.0f;
#pragma unroll
        for (int j = 0; j < 5; j++) {
            float4 g4 = g4p[lane + j * 32];
            hq[j].x = h[j].x * rinv2 * g4.x; hq[j].y = h[j].y * rinv2 * g4.y;
            hq[j].z = h[j].z * rinv2 * g4.z; hq[j].w = h[j].w * rinv2 * g4.w;
            gm = fmaxf(gm, fmaxf(fmaxf(fabsf(hq[j].x), fabsf(hq[j].y)),
                                 fmaxf(fabsf(hq[j].z), fabsf(hq[j].w))));
        }
        gm = warp_red(gm, 1);
        gm = fmaxf(gm, 1e-10f);
        float sc = 127.0f / gm;
        char4* dst4 = (char4*)(dsts[which] + (size_t)t * HID);
#pragma unroll
        for (int j = 0; j < 5; j++) {
            char4 q;
            q.x = (int8_t)fminf(fmaxf(rintf(hq[j].x * sc), -128.0f), 127.0f);
            q.y = (int8_t)fminf(fmaxf(rintf(hq[j].y * sc), -128.0f), 127.0f);
            q.z = (int8_t)fminf(fmaxf(rintf(hq[j].z * sc), -128.0f), 127.0f);
            q.w = (int8_t)fminf(fmaxf(rintf(hq[j].w * sc), -128.0f), 127.0f);
            dst4[lane + j * 32] = q;
        }
        if (lane == 0) gmas[which][t] = gm;
    }
}

// ---------------- activation quant, warp-per-token (O path) ----------------
__global__ __launch_bounds__(256) void act_quant_o(const float* __restrict__ og) {
    int warp = threadIdx.x >> 5, lane = threadIdx.x & 31;
    int t = blockIdx.x * 8 + warp;
    const float4* xr = (const float4*)(g_att + (size_t)t * HID);
    const float4* og4 = (const float4*)og;
    float4 v[5], hq[5];
    float ss = 0.0f;
#pragma unroll
    for (int j = 0; j < 5; j++) {
        v[j] = xr[lane + j * 32];
        ss += v[j].x * v[j].x + v[j].y * v[j].y + v[j].z * v[j].z + v[j].w * v[j].w;
    }
    ss = warp_red(ss, 0);
    float rinv = rsqrtf(ss / (float)HID + 1e-6f);
    float gm = 0.0f;
#pragma unroll
    for (int j = 0; j < 5; j++) {
        float4 g4 = og4[lane + j * 32];
        hq[j].x = v[j].x * rinv * g4.x; hq[j].y = v[j].y * rinv * g4.y;
        hq[j].z = v[j].z * rinv * g4.z; hq[j].w = v[j].w * rinv * g4.w;
        gm = fmaxf(gm, fmaxf(fmaxf(fabsf(hq[j].x), fabsf(hq[j].y)),
                             fmaxf(fabsf(hq[j].z), fabsf(hq[j].w))));
    }
    gm = warp_red(gm, 1);
    gm = fmaxf(gm, 1e-10f);
    float sc = 127.0f / gm;
    char4* dst4 = (char4*)(g_xq_o + (size_t)t * HID);
#pragma unroll
    for (int j = 0; j < 5; j++) {
        char4 q;
        q.x = (int8_t)fminf(fmaxf(rintf(hq[j].x * sc), -128.0f), 127.0f);
        q.y = (int8_t)fminf(fmaxf(rintf(hq[j].y * sc), -128.0f), 127.0f);
        q.z = (int8_t)fminf(fmaxf(rintf(hq[j].z * sc), -128.0f), 127.0f);
        q.w = (int8_t)fminf(fmaxf(rintf(hq[j].w * sc), -128.0f), 127.0f);
        dst4[lane + j * 32] = q;
    }
    if (lane == 0) g_gamma_o[t] = gm;
}

// ---------------- mma / async helpers ----------------
__device__ __forceinline__ uint32_t smem_u32(const void* p) {
    return (uint32_t)__cvta_generic_to_shared(p);
}
__device__ __forceinline__ void ldmx4(uint32_t* r, uint32_t addr) {
    asm volatile("ldmatrix.sync.aligned.m8n8.x4.shared.b16 {%0,%1,%2,%3}, [%4];\n"
                 : "=r"(r[0]), "=r"(r[1]), "=r"(r[2]), "=r"(r[3]) : "r"(addr));
}
__device__ __forceinline__ void ldmx4t(uint32_t* r, uint32_t addr) {
    asm volatile("ldmatrix.sync.aligned.m8n8.x4.trans.shared.b16 {%0,%1,%2,%3}, [%4];\n"
                 : "=r"(r[0]), "=r"(r[1]), "=r"(r[2]), "=r"(r[3]) : "r"(addr));
}
__device__ __forceinline__ void mma_f16(float* c, const uint32_t* a, uint32_t b0, uint32_t b1) {
    asm volatile("mma.sync.aligned.m16n8k16.row.col.f32.f16.f16.f32 "
                 "{%0,%1,%2,%3}, {%4,%5,%6,%7}, {%8,%9}, {%0,%1,%2,%3};\n"
                 : "+f"(c[0]), "+f"(c[1]), "+f"(c[2]), "+f"(c[3])
                 : "r"(a[0]), "r"(a[1]), "r"(a[2]), "r"(a[3]), "r"(b0), "r"(b1));
}
__device__ __forceinline__ void mma_s8(int* c, const uint32_t* a, uint32_t b0, uint32_t b1) {
    asm volatile("mma.sync.aligned.m16n8k32.row.col.s32.s8.s8.s32 "
                 "{%0,%1,%2,%3}, {%4,%5,%6,%7}, {%8,%9}, {%0,%1,%2,%3};\n"
                 : "+r"(c[0]), "+r"(c[1]), "+r"(c[2]), "+r"(c[3])
                 : "r"(a[0]), "r"(a[1]), "r"(a[2]), "r"(a[3]), "r"(b0), "r"(b1));
}
__device__ __forceinline__ void cp16(void* s, const void* g) {
    asm volatile("cp.async.cg.shared.global [%0], [%1], 16;\n"
                 :: "r"(smem_u32(s)), "l"(g));
}
__device__ __forceinline__ void cp_commit() {
    asm volatile("cp.async.commit_group;\n");
}
template <int N>
__device__ __forceinline__ void cp_wait() {
    asm volatile("cp.async.wait_group %0;\n" :: "n"(N));
}
__device__ __forceinline__ uint32_t pack_h2(__half x, __half y) {
    __half2 h = __halves2half2(x, y);
    return *(uint32_t*)&h;
}
__device__ __forceinline__ void split_h(float x, __half& hi, __half& lo) {
    hi = __float2half_rn(x);
    lo = __float2half_rn(x - __half2float(hi));
}

// ---------------- int8 TC GEMM, cp.async double-buffered ----------------------
// mode 0: split-fp16 hi/lo output to [B,H,L,HD] (+optional rope, scale)
// mode 1: float out token-major + residual
#define GP 144
#define GSTAGE (128 * GP)
__global__ __launch_bounds__(256) void gemm_imma(
    const int8_t* __restrict__ A, const int8_t* __restrict__ Bw,
    const float* __restrict__ gamma, const float* __restrict__ alpha_p,
    float* __restrict__ outf, __half* __restrict__ hob, __half* __restrict__ lob,
    int mode, int nheads, const float* __restrict__ resid, int rope, float oscale) {
    extern __shared__ int8_t dsm[];
    int8_t* As = dsm;
    int8_t* Bs = dsm + 2 * GSTAGE;
    int t0 = blockIdx.x * 128;
    int n0 = blockIdx.y * 128;
    int tid = threadIdx.x, warp = tid >> 5, lane = tid & 31;
    int wm = warp >> 1, wn = warp & 1;

    int acc[2][8][4];
#pragma unroll
    for (int mt = 0; mt < 2; mt++)
#pragma unroll
        for (int nt = 0; nt < 8; nt++)
#pragma unroll
            for (int i = 0; i < 4; i++) acc[mt][nt][i] = 0;

    int row = tid >> 1;
    int sh = (tid & 1) * 4;
#pragma unroll
    for (int c = 0; c <= 5; c++) {
        if (c < 5) {
            int st = (c & 1) * GSTAGE;
#pragma unroll
            for (int s = 0; s < 4; s++) {
                int seg = sh + s;
                cp16(&As[st + row * GP + seg * 16],
                     &A[(size_t)(t0 + row) * HID + c * 128 + seg * 16]);
                cp16(&Bs[st + row * GP + seg * 16],
                     &Bw[(size_t)(n0 + row) * HID + c * 128 + seg * 16]);
            }
            cp_commit();
        }
        if (c == 0) continue;
        int cc = c - 1;
        if (c < 5) cp_wait<1>(); else cp_wait<0>();
        __syncthreads();
        int st = (cc & 1) * GSTAGE;
#pragma unroll
        for (int ks = 0; ks < 4; ks++) {
            uint32_t af[2][4];
#pragma unroll
            for (int mt = 0; mt < 2; mt++)
                ldmx4(af[mt], smem_u32(&As[st + (wm * 32 + mt * 16 + (lane & 15)) * GP +
                                            ks * 32 + (lane >> 4) * 16]));
#pragma unroll
            for (int np = 0; np < 4; np++) {
                uint32_t bf[4];
                ldmx4(bf, smem_u32(&Bs[st + (wn * 64 + np * 16 + (lane & 15)) * GP +
                                        ks * 32 + (lane >> 4) * 16]));
#pragma unroll
                for (int mt = 0; mt < 2; mt++) {
                    mma_s8(acc[mt][np * 2],     af[mt], bf[0], bf[2]);
                    mma_s8(acc[mt][np * 2 + 1], af[mt], bf[1], bf[3]);
                }
            }
        }
        __syncthreads();
    }

    float alpha = *alpha_p * (1.0f / 127.0f) * oscale;
#pragma unroll
    for (int mt = 0; mt < 2; mt++) {
        int r0 = t0 + wm * 32 + mt * 16 + (lane >> 2);
        int r1 = r0 + 8;
        float s0 = alpha * gamma[r0];
        float s1 = alpha * gamma[r1];
#pragma unroll
        for (int nt = 0; nt < 8; nt++) {
            int n = n0 + wn * 64 + nt * 8 + (lane & 3) * 2;
            float v00 = (float)acc[mt][nt][0] * s0, v01 = (float)acc[mt][nt][1] * s0;
            float v10 = (float)acc[mt][nt][2] * s1, v11 = (float)acc[mt][nt][3] * s1;
            if (mode == 0) {
                int head = n >> 6, d = n & 63;
                int b0i = r0 >> 9, l0 = r0 & 511;
                int b1i = r1 >> 9, l1 = r1 & 511;
                if (rope) {
                    int p = d >> 1;
                    float c0 = g_cos[l0 * 32 + p], sn0 = g_sin[l0 * 32 + p];
                    float c1 = g_cos[l1 * 32 + p], sn1 = g_sin[l1 * 32 + p];
                    float t00 = v00 * c0 - v01 * sn0, t01 = v01 * c0 + v00 * sn0;
                    float t10 = v10 * c1 - v11 * sn1, t11 = v11 * c1 + v10 * sn1;
                    v00 = t00; v01 = t01; v10 = t10; v11 = t11;
                }
                size_t i0 = (((size_t)b0i * nheads + head) * SEQ + l0) * HD + d;
                size_t i1 = (((size_t)b1i * nheads + head) * SEQ + l1) * HD + d;
                __half h00, h01, h10, h11, e00, e01, e10, e11;
                split_h(v00, h00, e00); split_h(v01, h01, e01);
                split_h(v10, h10, e10); split_h(v11, h11, e11);
                *(__half2*)&hob[i0] = __halves2half2(h00, h01);
                *(__half2*)&lob[i0] = __halves2half2(e00, e01);
                *(__half2*)&hob[i1] = __halves2half2(h10, h11);
                *(__half2*)&lob[i1] = __halves2half2(e10, e11);
            } else {
                const float* rr0 = resid + (size_t)r0 * HID + n;
                const float* rr1 = resid + (size_t)r1 * HID + n;
                *(float2*)&outf[(size_t)r0 * HID + n] = make_float2(v00 + rr0[0], v01 + rr0[1]);
                *(float2*)&outf[(size_t)r1 * HID + n] = make_float2(v10 + rr1[0], v11 + rr1[1]);
            }
        }
    }
}

// ---------------- RoPE tables ----------------
__global__ void rope_tab() {
    int idx = blockIdx.x * blockDim.x + threadIdx.x;
    if (idx >= SEQ * 32) return;
    int l = idx >> 5, p = idx & 31;
    double freq = exp2(-(double)p * (18.93156856932417 / 32.0));  // 500000^(-p/32)
    double a = (double)l * freq;
    const double TWO_PI = 6.283185307179586476925287;
    double r = a - floor(a * (1.0 / TWO_PI)) * TWO_PI;
    float rf = (float)r;
    g_cos[idx] = cosf(rf);
    g_sin[idx] = sinf(rf);
}

// ---------------- attention: flash, split-fp16 mma, cp.async 2-stage ----------
// smem (halves): Q phase Qh@0 Ql@9216; KV stage s@s*18432: Kh,Kl,Vh,Vl each 4608.
#define SPITCH 72
#define ATTN_SMEM (36864 * 2)   // 73728 B
__global__ __launch_bounds__(256) void attn_mma(
    const __half* __restrict__ qh, const __half* __restrict__ ql,
    const __half* __restrict__ kh, const __half* __restrict__ kl,
    const __half* __restrict__ vh, const __half* __restrict__ vl,
    float* __restrict__ out) {
    extern __shared__ __half ASM[];

    int tid = threadIdx.x;
    int warp = tid >> 5, lane = tid & 31;
    int qt = blockIdx.x;
    int bh = blockIdx.y;
    int b = bh / NQH, h = bh % NQH;
    int kvh = h / (NQH / NKVH);

    size_t qoff = ((size_t)(b * NQH + h) * SEQ + qt * 128) * HD;
    size_t kvoff = (size_t)(b * NKVH + kvh) * SEQ * HD;
    const __half* gbuf[4] = { kh + kvoff, kl + kvoff, vh + kvoff, vl + kvoff };

    __half* Qh = ASM;
    __half* Ql = ASM + 9216;
#pragma unroll
    for (int i = 0; i < 4; i++) {
        int slot = tid + i * 256;          // 1024 slots of 16B
        int r = slot >> 3, seg = slot & 7;
        *(float4*)&Qh[r * SPITCH + seg * 8] = *(const float4*)&qh[qoff + r * 64 + seg * 8];
        *(float4*)&Ql[r * SPITCH + seg * 8] = *(const float4*)&ql[qoff + r * 64 + seg * 8];
    }
    __syncthreads();

    // prefetch kt=0 into stage 1
    {
        __half* sb = ASM + 18432;
#pragma unroll
        for (int i = 0; i < 8; i++) {
            int slot = tid + i * 256;      // 2048 slots
            int bufi = slot >> 9, r = (slot >> 3) & 63, seg = slot & 7;
            cp16(&sb[bufi * 4608 + r * SPITCH + seg * 8], &gbuf[bufi][r * 64 + seg * 8]);
        }
        cp_commit();
    }

    // persistent Q fragments
    uint32_t qah[4][4], qal[4][4];
    int m0 = warp * 16;
#pragma unroll
    for (int kc = 0; kc < 4; kc++) {
        int r = m0 + (lane & 15), c = kc * 16 + (lane >> 4) * 8;
        ldmx4(qah[kc], smem_u32(&Qh[r * SPITCH + c]));
        ldmx4(qal[kc], smem_u32(&Ql[r * SPITCH + c]));
    }
    __syncthreads();   // Q region (stage 0) free

    float oacc[8][4];
#pragma unroll
    for (int nt = 0; nt < 8; nt++)
#pragma unroll
        for (int i = 0; i < 4; i++) oacc[nt][i] = 0.0f;
    float mrow0 = -1e30f, mrow1 = -1e30f, lrow0 = 0.0f, lrow1 = 0.0f;

    for (int kt = 0; kt < 8; kt++) {
        if (kt < 7) {                       // prefetch kt+1 into stage kt&1
            __half* sb = ASM + (kt & 1) * 18432;
#pragma unroll
            for (int i = 0; i < 8; i++) {
                int slot = tid + i * 256;
                int bufi = slot >> 9, r = (slot >> 3) & 63, seg = slot & 7;
                cp16(&sb[bufi * 4608 + r * SPITCH + seg * 8],
                     &gbuf[bufi][((kt + 1) * 64 + r) * 64 + seg * 8]);
            }
            cp_commit();
            cp_wait<1>();
        } else {
            cp_wait<0>();
        }
        __syncthreads();
        __half* sb = ASM + ((kt + 1) & 1) * 18432;
        __half* Khs = sb;
        __half* Kls = sb + 4608;
        __half* Vhs = sb + 9216;
        __half* Vls = sb + 13824;

        // S = Q@K^T (3-term split)
        float sacc[8][4];
#pragma unroll
        for (int nt = 0; nt < 8; nt++)
#pragma unroll
            for (int i = 0; i < 4; i++) sacc[nt][i] = 0.0f;
        int g = lane >> 3;
        int n_off = (g >= 2) ? 8 : 0, k_off = (g & 1) * 8;
#pragma unroll
        for (int nt2 = 0; nt2 < 4; nt2++) {
#pragma unroll
            for (int kc = 0; kc < 4; kc++) {
                uint32_t kbh[4], kbl[4];
                int r = nt2 * 16 + n_off + (lane & 7), c = kc * 16 + k_off;
                ldmx4(kbh, smem_u32(&Khs[r * SPITCH + c]));
                ldmx4(kbl, smem_u32(&Kls[r * SPITCH + c]));
                mma_f16(sacc[nt2 * 2],     qah[kc], kbh[0], kbh[1]);
                mma_f16(sacc[nt2 * 2],     qah[kc], kbl[0], kbl[1]);
                mma_f16(sacc[nt2 * 2],     qal[kc], kbh[0], kbh[1]);
                mma_f16(sacc[nt2 * 2 + 1], qah[kc], kbh[2], kbh[3]);
                mma_f16(sacc[nt2 * 2 + 1], qah[kc], kbl[2], kbl[3]);
                mma_f16(sacc[nt2 * 2 + 1], qal[kc], kbh[2], kbh[3]);
            }
        }

        // online softmax (rows lane/4, lane/4+8)
        float mx0 = -1e30f, mx1 = -1e30f;
#pragma unroll
        for (int nt = 0; nt < 8; nt++) {
            mx0 = fmaxf(mx0, fmaxf(sacc[nt][0], sacc[nt][1]));
            mx1 = fmaxf(mx1, fmaxf(sacc[nt][2], sacc[nt][3]));
        }
        mx0 = fmaxf(mx0, __shfl_xor_sync(0xffffffffu, mx0, 1));
        mx0 = fmaxf(mx0, __shfl_xor_sync(0xffffffffu, mx0, 2));
        mx1 = fmaxf(mx1, __shfl_xor_sync(0xffffffffu, mx1, 1));
        mx1 = fmaxf(mx1, __shfl_xor_sync(0xffffffffu, mx1, 2));
        float mn0 = fmaxf(mrow0, mx0), mn1 = fmaxf(mrow1, mx1);
        float e0 = __expf(mrow0 - mn0), e1 = __expf(mrow1 - mn1);
        mrow0 = mn0; mrow1 = mn1;

        float sum0 = 0.0f, sum1 = 0.0f;
        uint32_t pah[4][4], pal[4][4];
#pragma unroll
        for (int kc2 = 0; kc2 < 4; kc2++) {
            int nta = kc2 * 2, ntb = nta + 1;
            float p[8];
            p[0] = __expf(sacc[nta][0] - mn0); p[1] = __expf(sacc[nta][1] - mn0);
            p[2] = __expf(sacc[nta][2] - mn1); p[3] = __expf(sacc[nta][3] - mn1);
            p[4] = __expf(sacc[ntb][0] - mn0); p[5] = __expf(sacc[ntb][1] - mn0);
            p[6] = __expf(sacc[ntb][2] - mn1); p[7] = __expf(sacc[ntb][3] - mn1);
            __half ph[8], pl[8];
#pragma unroll
            for (int i = 0; i < 8; i++) split_h(p[i], ph[i], pl[i]);
            sum0 += p[0] + p[1] + p[4] + p[5];
            sum1 += p[2] + p[3] + p[6] + p[7];
            pah[kc2][0] = pack_h2(ph[0], ph[1]); pal[kc2][0] = pack_h2(pl[0], pl[1]);
            pah[kc2][1] = pack_h2(ph[2], ph[3]); pal[kc2][1] = pack_h2(pl[2], pl[3]);
            pah[kc2][2] = pack_h2(ph[4], ph[5]); pal[kc2][2] = pack_h2(pl[4], pl[5]);
            pah[kc2][3] = pack_h2(ph[6], ph[7]); pal[kc2][3] = pack_h2(pl[6], pl[7]);
        }
        sum0 += __shfl_xor_sync(0xffffffffu, sum0, 1);
        sum0 += __shfl_xor_sync(0xffffffffu, sum0, 2);
        sum1 += __shfl_xor_sync(0xffffffffu, sum1, 1);
        sum1 += __shfl_xor_sync(0xffffffffu, sum1, 2);
        lrow0 = lrow0 * e0 + sum0;
        lrow1 = lrow1 * e1 + sum1;

#pragma unroll
        for (int nt = 0; nt < 8; nt++) {
            oacc[nt][0] *= e0; oacc[nt][1] *= e0;
            oacc[nt][2] *= e1; oacc[nt][3] *= e1;
        }

        // O += Ph@Vh + Ph@Vl + Pl@Vh
#pragma unroll
        for (int kc2 = 0; kc2 < 4; kc2++) {
#pragma unroll
            for (int nt2 = 0; nt2 < 4; nt2++) {
                uint32_t vbh[4], vbl[4];
                int r = kc2 * 16 + (g & 1) * 8 + (lane & 7);
                int c = nt2 * 16 + ((g >= 2) ? 8 : 0);
                ldmx4t(vbh, smem_u32(&Vhs[r * SPITCH + c]));
                ldmx4t(vbl, smem_u32(&Vls[r * SPITCH + c]));
                mma_f16(oacc[nt2 * 2],     pah[kc2], vbh[0], vbh[1]);
                mma_f16(oacc[nt2 * 2],     pah[kc2], vbl[0], vbl[1]);
                mma_f16(oacc[nt2 * 2],     pal[kc2], vbh[0], vbh[1]);
                mma_f16(oacc[nt2 * 2 + 1], pah[kc2], vbh[2], vbh[3]);
                mma_f16(oacc[nt2 * 2 + 1], pah[kc2], vbl[2], vbl[3]);
                mma_f16(oacc[nt2 * 2 + 1], pal[kc2], vbh[2], vbh[3]);
            }
        }
        __syncthreads();
    }

    float inv0 = 1.0f / lrow0, inv1 = 1.0f / lrow1;
    int r0 = qt * 128 + m0 + (lane >> 2);
    int r1 = r0 + 8;
#pragma unroll
    for (int nt = 0; nt < 8; nt++) {
        int col = h * HD + nt * 8 + (lane & 3) * 2;
        float2 v0 = make_float2(oacc[nt][0] * inv0, oacc[nt][1] * inv0);
        float2 v1 = make_float2(oacc[nt][2] * inv1, oacc[nt][3] * inv1);
        *(float2*)&out[((size_t)b * SEQ + r0) * HID + col] = v0;
        *(float2*)&out[((size_t)b * SEQ + r1) * HID + col] = v1;
    }
}

// ---------------- launch ----------------
extern "C" void kernel_launch(void* const* d_in, const int* in_sizes, int n_in,
                              void* d_out, int out_size) {
    const float* x      = (const float*)d_in[0];
    const float* norm_w = (const float*)d_in[1];
    const float* q_w    = (const float*)d_in[2];
    const float* q_g    = (const float*)d_in[3];
    const float* k_w    = (const float*)d_in[4];
    const float* k_g    = (const float*)d_in[5];
    const float* v_w    = (const float*)d_in[6];
    const float* v_g    = (const float*)d_in[7];
    const float* o_w    = (const float*)d_in[8];
    const float* o_g    = (const float*)d_in[9];
    float* out = (float*)d_out;

    void *p_xq_q, *p_xq_k, *p_xq_v, *p_xq_o;
    void *p_wq_q, *p_wq_k, *p_wq_v, *p_wq_o;
    void *p_gq, *p_gk, *p_gv, *p_go, *p_alpha, *p_att;
    void *p_qh, *p_ql, *p_kh, *p_kl, *p_vh, *p_vl;
    cudaGetSymbolAddress(&p_xq_q, g_xq_q);  cudaGetSymbolAddress(&p_xq_k, g_xq_k);
    cudaGetSymbolAddress(&p_xq_v, g_xq_v);  cudaGetSymbolAddress(&p_xq_o, g_xq_o);
    cudaGetSymbolAddress(&p_wq_q, g_wq_q);  cudaGetSymbolAddress(&p_wq_k, g_wq_k);
    cudaGetSymbolAddress(&p_wq_v, g_wq_v);  cudaGetSymbolAddress(&p_wq_o, g_wq_o);
    cudaGetSymbolAddress(&p_gq, g_gamma_q); cudaGetSymbolAddress(&p_gk, g_gamma_k);
    cudaGetSymbolAddress(&p_gv, g_gamma_v); cudaGetSymbolAddress(&p_go, g_gamma_o);
    cudaGetSymbolAddress(&p_alpha, g_alpha); cudaGetSymbolAddress(&p_att, g_att);
    cudaGetSymbolAddress(&p_qh, g_qh); cudaGetSymbolAddress(&p_ql, g_ql);
    cudaGetSymbolAddress(&p_kh, g_kh); cudaGetSymbolAddress(&p_kl, g_kl);
    cudaGetSymbolAddress(&p_vh, g_vh); cudaGetSymbolAddress(&p_vl, g_vl);

    const int GEMM_SMEM = 4 * GSTAGE;
    cudaFuncSetAttribute(gemm_imma, cudaFuncAttributeMaxDynamicSharedMemorySize, GEMM_SMEM);
    cudaFuncSetAttribute(attn_mma, cudaFuncAttributeMaxDynamicSharedMemorySize, ATTN_SMEM);

    // 1. rope tables
    rope_tab<<<(SEQ * 32 + 255) / 256, 256>>>();

    // 2. weight scales + ternary quant
    alpha_all<<<4, 1024>>>(q_w, k_w, v_w, o_w);
    wquant_all<<<(2 * HID * HID + 2 * KVDIM * HID + 255) / 256, 256>>>(q_w, k_w, v_w, o_w);

    // 3. activation double-rmsnorm + int8 quant
    act_quant_qkv<<<T_TOKENS / 8, 256>>>(x, norm_w, q_g, k_g, v_g);

    // 4. QKV GEMMs -> split fp16 hi/lo (rope fused for Q,K; 1/8 folded into Q)
    gemm_imma<<<dim3(128, 5), 256, GEMM_SMEM>>>((const int8_t*)p_xq_q, (const int8_t*)p_wq_q,
        (const float*)p_gq, (const float*)p_alpha + 0,
        nullptr, (__half*)p_qh, (__half*)p_ql, 0, NQH, nullptr, 1, 0.125f);
    gemm_imma<<<dim3(128, 1), 256, GEMM_SMEM>>>((const int8_t*)p_xq_k, (const int8_t*)p_wq_k,
        (const float*)p_gk, (const float*)p_alpha + 1,
        nullptr, (__half*)p_kh, (__half*)p_kl, 0, NKVH, nullptr, 1, 1.0f);
    gemm_imma<<<dim3(128, 1), 256, GEMM_SMEM>>>((const int8_t*)p_xq_v, (const int8_t*)p_wq_v,
        (const float*)p_gv, (const float*)p_alpha + 2,
        nullptr, (__half*)p_vh, (__half*)p_vl, 0, NKVH, nullptr, 0, 1.0f);

    // 5. attention
    attn_mma<<<dim3(SEQ / 128, BATCH * NQH), 256, ATTN_SMEM>>>(
        (const __half*)p_qh, (const __half*)p_ql,
        (const __half*)p_kh, (const __half*)p_kl,
        (const __half*)p_vh, (const __half*)p_vl, (float*)p_att);

    // 6. O-proj quant + GEMM + residual
    act_quant_o<<<T_TOKENS / 8, 256>>>(o_g);
    gemm_imma<<<dim3(128, 5), 256, GEMM_SMEM>>>((const int8_t*)p_xq_o, (const int8_t*)p_wq_o,
        (const float*)p_go, (const float*)p_alpha + 3,
        out, nullptr, nullptr, 1, 0, x, 0, 1.0f);
}

// round 8
// speedup vs baseline: 2.4190x; 1.0729x over previous
#include <cuda_runtime.h>
#include <cuda_fp16.h>
#include <math.h>
#include <stdint.h>

#define T_TOKENS 16384
#define HID      640
#define NQH      10
#define NKVH     2
#define HD       64
#define SEQ      512
#define BATCH    32
#define KVDIM    128

// ---------------- scratch ----------------
__device__ __align__(16) int8_t g_xq_q[T_TOKENS * HID];
__device__ __align__(16) int8_t g_xq_k[T_TOKENS * HID];
__device__ __align__(16) int8_t g_xq_v[T_TOKENS * HID];
__device__ __align__(16) int8_t g_xq_o[T_TOKENS * HID];
__device__ __align__(16) int8_t g_wq_q[HID * HID];
__device__ __align__(16) int8_t g_wq_k[KVDIM * HID];
__device__ __align__(16) int8_t g_wq_v[KVDIM * HID];
__device__ __align__(16) int8_t g_wq_o[HID * HID];
__device__ float g_gamma_q[T_TOKENS];
__device__ float g_gamma_k[T_TOKENS];
__device__ float g_gamma_v[T_TOKENS];
__device__ float g_gamma_o[T_TOKENS];
__device__ float g_alpha[4];
__device__ __align__(16) __half g_qh[BATCH * NQH * SEQ * HD];
__device__ __align__(16) __half g_ql[BATCH * NQH * SEQ * HD];
__device__ __align__(16) __half g_kh[BATCH * NKVH * SEQ * HD];
__device__ __align__(16) __half g_kl[BATCH * NKVH * SEQ * HD];
__device__ __align__(16) __half g_vh[BATCH * NKVH * SEQ * HD];
__device__ __align__(16) __half g_vl[BATCH * NKVH * SEQ * HD];
__device__ float g_att[T_TOKENS * HID];
__device__ float g_cos[SEQ * 32];
__device__ float g_sin[SEQ * 32];

// ---------------- reduction helpers ----------------
__device__ __forceinline__ float warp_red(float v, int op) {
#pragma unroll
    for (int o = 16; o; o >>= 1) {
        float t = __shfl_xor_sync(0xffffffffu, v, o);
        v = op ? fmaxf(v, t) : v + t;
    }
    return v;
}
__device__ __forceinline__ float block_reduce(float v, int op, float* sm, int nwarps) {
    int lane = threadIdx.x & 31, w = threadIdx.x >> 5;
    v = warp_red(v, op);
    if (!lane) sm[w] = v;
    __syncthreads();
    if (w == 0) {
        v = (lane < nwarps) ? sm[lane] : (op ? -INFINITY : 0.0f);
        v = warp_red(v, op);
        if (!lane) sm[0] = v;
    }
    __syncthreads();
    v = sm[0];
    __syncthreads();
    return v;
}

// ---------------- prep: weight alpha (blocks 0-3) + rope tables (blocks 4+) ----
__global__ __launch_bounds__(1024) void prep_all(
    const float* __restrict__ qw, const float* __restrict__ kw,
    const float* __restrict__ vw, const float* __restrict__ ow) {
    if (blockIdx.x < 4) {
        __shared__ float sm[32];
        int which = blockIdx.x;
        const float* w = which == 0 ? qw : which == 1 ? kw : which == 2 ? vw : ow;
        int n = (which == 1 || which == 2) ? (KVDIM * HID) : (HID * HID);
        float s = 0.0f;
        for (int i = threadIdx.x; i < n; i += 1024) s += fabsf(w[i]);
        s = block_reduce(s, 0, sm, 32);
        if (threadIdx.x == 0) g_alpha[which] = fmaxf(s / (float)n, 1e-10f);
    } else {
        int idx = (blockIdx.x - 4) * 1024 + threadIdx.x;
        if (idx >= SEQ * 32) return;
        int l = idx >> 5, p = idx & 31;
        double freq = exp2(-(double)p * (18.93156856932417 / 32.0));  // 500000^(-p/32)
        double a = (double)l * freq;
        const double TWO_PI = 6.283185307179586476925287;
        double r = a - floor(a * (1.0 / TWO_PI)) * TWO_PI;
        float rf = (float)r;
        g_cos[idx] = cosf(rf);
        g_sin[idx] = sinf(rf);
    }
}

// ---------------- weight ternary quant ----------------
__global__ void wquant_all(const float* __restrict__ qw, const float* __restrict__ kw,
                           const float* __restrict__ vw, const float* __restrict__ ow) {
    int idx = blockIdx.x * blockDim.x + threadIdx.x;
    const float* w; int8_t* dst; int off; int which;
    const int nQ = HID * HID, nK = KVDIM * HID;
    if (idx < nQ)                       { which = 0; w = qw; dst = g_wq_q; off = idx; }
    else if (idx < nQ + nK)             { which = 1; w = kw; dst = g_wq_k; off = idx - nQ; }
    else if (idx < nQ + 2 * nK)         { which = 2; w = vw; dst = g_wq_v; off = idx - nQ - nK; }
    else if (idx < 2 * nQ + 2 * nK)     { which = 3; w = ow; dst = g_wq_o; off = idx - nQ - 2 * nK; }
    else return;
    float a = g_alpha[which];
    float q = rintf(w[off] / a);
    q = fminf(fmaxf(q, -1.0f), 1.0f);
    dst[off] = (int8_t)q;
}

// ---------------- activation quant, warp-per-token (QKV) ----------------
__global__ __launch_bounds__(256) void act_quant_qkv(
    const float* __restrict__ x, const float* __restrict__ nw,
    const float* __restrict__ qg, const float* __restrict__ kg, const float* __restrict__ vg) {
    int warp = threadIdx.x >> 5, lane = threadIdx.x & 31;
    int t = blockIdx.x * 8 + warp;
    const float4* xr = (const float4*)(x + (size_t)t * HID);
    const float4* nw4 = (const float4*)nw;
    float4 v[5], h[5];
    float ss = 0.0f;
#pragma unroll
    for (int j = 0; j < 5; j++) {
        v[j] = xr[lane + j * 32];
        ss += v[j].x * v[j].x + v[j].y * v[j].y + v[j].z * v[j].z + v[j].w * v[j].w;
    }
    ss = warp_red(ss, 0);
    float rinv = rsqrtf(ss / (float)HID + 1e-6f);
    float s2 = 0.0f;
#pragma unroll
    for (int j = 0; j < 5; j++) {
        float4 g4 = nw4[lane + j * 32];
        h[j].x = v[j].x * rinv * g4.x; h[j].y = v[j].y * rinv * g4.y;
        h[j].z = v[j].z * rinv * g4.z; h[j].w = v[j].w * rinv * g4.w;
        s2 += h[j].x * h[j].x + h[j].y * h[j].y + h[j].z * h[j].z + h[j].w * h[j].w;
    }
    s2 = warp_red(s2, 0);
    float rinv2 = rsqrtf(s2 / (float)HID + 1e-6f);

    const float* gains[3] = { qg, kg, vg };
    int8_t* dsts[3] = { g_xq_q, g_xq_k, g_xq_v };
    float* gmas[3] = { g_gamma_q, g_gamma_k, g_gamma_v };
#pragma unroll
    for (int which = 0; which < 3; which++) {
        const float4* g4p = (const float4*)gains[which];
        float4 hq[5];
        float gm = 0.0f;
#pragma unroll
        for (int j = 0; j < 5; j++) {
            float4 g4 = g4p[lane + j * 32];
            hq[j].x = h[j].x * rinv2 * g4.x; hq[j].y = h[j].y * rinv2 * g4.y;
            hq[j].z = h[j].z * rinv2 * g4.z; hq[j].w = h[j].w * rinv2 * g4.w;
            gm = fmaxf(gm, fmaxf(fmaxf(fabsf(hq[j].x), fabsf(hq[j].y)),
                                 fmaxf(fabsf(hq[j].z), fabsf(hq[j].w))));
        }
        gm = warp_red(gm, 1);
        gm = fmaxf(gm, 1e-10f);
        float sc = 127.0f / gm;
        char4* dst4 = (char4*)(dsts[which] + (size_t)t * HID);
#pragma unroll
        for (int j = 0; j < 5; j++) {
            char4 q;
            q.x = (int8_t)fminf(fmaxf(rintf(hq[j].x * sc), -128.0f), 127.0f);
            q.y = (int8_t)fminf(fmaxf(rintf(hq[j].y * sc), -128.0f), 127.0f);
            q.z = (int8_t)fminf(fmaxf(rintf(hq[j].z * sc), -128.0f), 127.0f);
            q.w = (int8_t)fminf(fmaxf(rintf(hq[j].w * sc), -128.0f), 127.0f);
            dst4[lane + j * 32] = q;
        }
        if (lane == 0) gmas[which][t] = gm;
    }
}

// ---------------- activation quant, warp-per-token (O path) ----------------
__global__ __launch_bounds__(256) void act_quant_o(const float* __restrict__ og) {
    int warp = threadIdx.x >> 5, lane = threadIdx.x & 31;
    int t = blockIdx.x * 8 + warp;
    const float4* xr = (const float4*)(g_att + (size_t)t * HID);
    const float4* og4 = (const float4*)og;
    float4 v[5], hq[5];
    float ss = 0.0f;
#pragma unroll
    for (int j = 0; j < 5; j++) {
        v[j] = xr[lane + j * 32];
        ss += v[j].x * v[j].x + v[j].y * v[j].y + v[j].z * v[j].z + v[j].w * v[j].w;
    }
    ss = warp_red(ss, 0);
    float rinv = rsqrtf(ss / (float)HID + 1e-6f);
    float gm = 0.0f;
#pragma unroll
    for (int j = 0; j < 5; j++) {
        float4 g4 = og4[lane + j * 32];
        hq[j].x = v[j].x * rinv * g4.x; hq[j].y = v[j].y * rinv * g4.y;
        hq[j].z = v[j].z * rinv * g4.z; hq[j].w = v[j].w * rinv * g4.w;
        gm = fmaxf(gm, fmaxf(fmaxf(fabsf(hq[j].x), fabsf(hq[j].y)),
                             fmaxf(fabsf(hq[j].z), fabsf(hq[j].w))));
    }
    gm = warp_red(gm, 1);
    gm = fmaxf(gm, 1e-10f);
    float sc = 127.0f / gm;
    char4* dst4 = (char4*)(g_xq_o + (size_t)t * HID);
#pragma unroll
    for (int j = 0; j < 5; j++) {
        char4 q;
        q.x = (int8_t)fminf(fmaxf(rintf(hq[j].x * sc), -128.0f), 127.0f);
        q.y = (int8_t)fminf(fmaxf(rintf(hq[j].y * sc), -128.0f), 127.0f);
        q.z = (int8_t)fminf(fmaxf(rintf(hq[j].z * sc), -128.0f), 127.0f);
        q.w = (int8_t)fminf(fmaxf(rintf(hq[j].w * sc), -128.0f), 127.0f);
        dst4[lane + j * 32] = q;
    }
    if (lane == 0) g_gamma_o[t] = gm;
}

// ---------------- mma / async helpers ----------------
__device__ __forceinline__ uint32_t smem_u32(const void* p) {
    return (uint32_t)__cvta_generic_to_shared(p);
}
__device__ __forceinline__ void ldmx4(uint32_t* r, uint32_t addr) {
    asm volatile("ldmatrix.sync.aligned.m8n8.x4.shared.b16 {%0,%1,%2,%3}, [%4];\n"
                 : "=r"(r[0]), "=r"(r[1]), "=r"(r[2]), "=r"(r[3]) : "r"(addr));
}
__device__ __forceinline__ void ldmx4t(uint32_t* r, uint32_t addr) {
    asm volatile("ldmatrix.sync.aligned.m8n8.x4.trans.shared.b16 {%0,%1,%2,%3}, [%4];\n"
                 : "=r"(r[0]), "=r"(r[1]), "=r"(r[2]), "=r"(r[3]) : "r"(addr));
}
__device__ __forceinline__ void mma_f16(float* c, const uint32_t* a, uint32_t b0, uint32_t b1) {
    asm volatile("mma.sync.aligned.m16n8k16.row.col.f32.f16.f16.f32 "
                 "{%0,%1,%2,%3}, {%4,%5,%6,%7}, {%8,%9}, {%0,%1,%2,%3};\n"
                 : "+f"(c[0]), "+f"(c[1]), "+f"(c[2]), "+f"(c[3])
                 : "r"(a[0]), "r"(a[1]), "r"(a[2]), "r"(a[3]), "r"(b0), "r"(b1));
}
__device__ __forceinline__ void mma_s8(int* c, const uint32_t* a, uint32_t b0, uint32_t b1) {
    asm volatile("mma.sync.aligned.m16n8k32.row.col.s32.s8.s8.s32 "
                 "{%0,%1,%2,%3}, {%4,%5,%6,%7}, {%8,%9}, {%0,%1,%2,%3};\n"
                 : "+r"(c[0]), "+r"(c[1]), "+r"(c[2]), "+r"(c[3])
                 : "r"(a[0]), "r"(a[1]), "r"(a[2]), "r"(a[3]), "r"(b0), "r"(b1));
}
__device__ __forceinline__ void cp16(void* s, const void* g) {
    asm volatile("cp.async.cg.shared.global [%0], [%1], 16;\n"
                 :: "r"(smem_u32(s)), "l"(g));
}
__device__ __forceinline__ void cp_commit() {
    asm volatile("cp.async.commit_group;\n");
}
template <int N>
__device__ __forceinline__ void cp_wait() {
    asm volatile("cp.async.wait_group %0;\n" :: "n"(N));
}
__device__ __forceinline__ uint32_t pack_h2(__half x, __half y) {
    __half2 h = __halves2half2(x, y);
    return *(uint32_t*)&h;
}
__device__ __forceinline__ void split_h(float x, __half& hi, __half& lo) {
    hi = __float2half_rn(x);
    lo = __float2half_rn(x - __half2float(hi));
}

// ---------------- fused QKV int8 TC GEMM (1D grid, path-decoded) -------------
// blocks [0,640): Q (x=bid&127, y=bid>>7); [640,768): K; [768,896): V
#define GP 144
#define GSTAGE (128 * GP)
__global__ __launch_bounds__(256) void gemm_qkv() {
    extern __shared__ int8_t dsm[];
    int8_t* As = dsm;
    int8_t* Bs = dsm + 2 * GSTAGE;
    int bid = blockIdx.x;
    int path, bx, by;
    if (bid < 640)      { path = 0; bx = bid & 127; by = bid >> 7; }
    else if (bid < 768) { path = 1; bx = bid - 640; by = 0; }
    else                { path = 2; bx = bid - 768; by = 0; }
    const int8_t* A  = path == 0 ? g_xq_q : path == 1 ? g_xq_k : g_xq_v;
    const int8_t* Bw = path == 0 ? g_wq_q : path == 1 ? g_wq_k : g_wq_v;
    const float* gamma = path == 0 ? g_gamma_q : path == 1 ? g_gamma_k : g_gamma_v;
    __half* hob = path == 0 ? g_qh : path == 1 ? g_kh : g_vh;
    __half* lob = path == 0 ? g_ql : path == 1 ? g_kl : g_vl;
    int nheads = path == 0 ? NQH : NKVH;
    int rope   = path == 2 ? 0 : 1;
    float oscale = path == 0 ? 0.125f : 1.0f;

    int t0 = bx * 128;
    int n0 = by * 128;
    int tid = threadIdx.x, warp = tid >> 5, lane = tid & 31;
    int wm = warp >> 1, wn = warp & 1;

    int acc[2][8][4];
#pragma unroll
    for (int mt = 0; mt < 2; mt++)
#pragma unroll
        for (int nt = 0; nt < 8; nt++)
#pragma unroll
            for (int i = 0; i < 4; i++) acc[mt][nt][i] = 0;

    int row = tid >> 1;
    int sh = (tid & 1) * 4;
#pragma unroll
    for (int c = 0; c <= 5; c++) {
        if (c < 5) {
            int st = (c & 1) * GSTAGE;
#pragma unroll
            for (int s = 0; s < 4; s++) {
                int seg = sh + s;
                cp16(&As[st + row * GP + seg * 16],
                     &A[(size_t)(t0 + row) * HID + c * 128 + seg * 16]);
                cp16(&Bs[st + row * GP + seg * 16],
                     &Bw[(size_t)(n0 + row) * HID + c * 128 + seg * 16]);
            }
            cp_commit();
        }
        if (c == 0) continue;
        int cc = c - 1;
        if (c < 5) cp_wait<1>(); else cp_wait<0>();
        __syncthreads();
        int st = (cc & 1) * GSTAGE;
#pragma unroll
        for (int ks = 0; ks < 4; ks++) {
            uint32_t af[2][4];
#pragma unroll
            for (int mt = 0; mt < 2; mt++)
                ldmx4(af[mt], smem_u32(&As[st + (wm * 32 + mt * 16 + (lane & 15)) * GP +
                                            ks * 32 + (lane >> 4) * 16]));
#pragma unroll
            for (int np = 0; np < 4; np++) {
                uint32_t bf[4];
                ldmx4(bf, smem_u32(&Bs[st + (wn * 64 + np * 16 + (lane & 15)) * GP +
                                        ks * 32 + (lane >> 4) * 16]));
#pragma unroll
                for (int mt = 0; mt < 2; mt++) {
                    mma_s8(acc[mt][np * 2],     af[mt], bf[0], bf[2]);
                    mma_s8(acc[mt][np * 2 + 1], af[mt], bf[1], bf[3]);
                }
            }
        }
        __syncthreads();
    }

    float alpha = g_alpha[path] * (1.0f / 127.0f) * oscale;
#pragma unroll
    for (int mt = 0; mt < 2; mt++) {
        int r0 = t0 + wm * 32 + mt * 16 + (lane >> 2);
        int r1 = r0 + 8;
        float s0 = alpha * gamma[r0];
        float s1 = alpha * gamma[r1];
#pragma unroll
        for (int nt = 0; nt < 8; nt++) {
            int n = n0 + wn * 64 + nt * 8 + (lane & 3) * 2;
            float v00 = (float)acc[mt][nt][0] * s0, v01 = (float)acc[mt][nt][1] * s0;
            float v10 = (float)acc[mt][nt][2] * s1, v11 = (float)acc[mt][nt][3] * s1;
            int head = n >> 6, d = n & 63;
            int b0i = r0 >> 9, l0 = r0 & 511;
            int b1i = r1 >> 9, l1 = r1 & 511;
            if (rope) {
                int p = d >> 1;
                float c0 = g_cos[l0 * 32 + p], sn0 = g_sin[l0 * 32 + p];
                float c1 = g_cos[l1 * 32 + p], sn1 = g_sin[l1 * 32 + p];
                float t00 = v00 * c0 - v01 * sn0, t01 = v01 * c0 + v00 * sn0;
                float t10 = v10 * c1 - v11 * sn1, t11 = v11 * c1 + v10 * sn1;
                v00 = t00; v01 = t01; v10 = t10; v11 = t11;
            }
            size_t i0 = (((size_t)b0i * nheads + head) * SEQ + l0) * HD + d;
            size_t i1 = (((size_t)b1i * nheads + head) * SEQ + l1) * HD + d;
            __half h00, h01, h10, h11, e00, e01, e10, e11;
            split_h(v00, h00, e00); split_h(v01, h01, e01);
            split_h(v10, h10, e10); split_h(v11, h11, e11);
            *(__half2*)&hob[i0] = __halves2half2(h00, h01);
            *(__half2*)&lob[i0] = __halves2half2(e00, e01);
            *(__half2*)&hob[i1] = __halves2half2(h10, h11);
            *(__half2*)&lob[i1] = __halves2half2(e10, e11);
        }
    }
}

// ---------------- O-proj int8 TC GEMM (token-major float out + residual) ------
__global__ __launch_bounds__(256) void gemm_o(
    float* __restrict__ outf, const float* __restrict__ resid) {
    extern __shared__ int8_t dsm[];
    int8_t* As = dsm;
    int8_t* Bs = dsm + 2 * GSTAGE;
    const int8_t* A  = g_xq_o;
    const int8_t* Bw = g_wq_o;
    int t0 = blockIdx.x * 128;
    int n0 = blockIdx.y * 128;
    int tid = threadIdx.x, warp = tid >> 5, lane = tid & 31;
    int wm = warp >> 1, wn = warp & 1;

    int acc[2][8][4];
#pragma unroll
    for (int mt = 0; mt < 2; mt++)
#pragma unroll
        for (int nt = 0; nt < 8; nt++)
#pragma unroll
            for (int i = 0; i < 4; i++) acc[mt][nt][i] = 0;

    int row = tid >> 1;
    int sh = (tid & 1) * 4;
#pragma unroll
    for (int c = 0; c <= 5; c++) {
        if (c < 5) {
            int st = (c & 1) * GSTAGE;
#pragma unroll
            for (int s = 0; s < 4; s++) {
                int seg = sh + s;
                cp16(&As[st + row * GP + seg * 16],
                     &A[(size_t)(t0 + row) * HID + c * 128 + seg * 16]);
                cp16(&Bs[st + row * GP + seg * 16],
                     &Bw[(size_t)(n0 + row) * HID + c * 128 + seg * 16]);
            }
            cp_commit();
        }
        if (c == 0) continue;
        int cc = c - 1;
        if (c < 5) cp_wait<1>(); else cp_wait<0>();
        __syncthreads();
        int st = (cc & 1) * GSTAGE;
#pragma unroll
        for (int ks = 0; ks < 4; ks++) {
            uint32_t af[2][4];
#pragma unroll
            for (int mt = 0; mt < 2; mt++)
                ldmx4(af[mt], smem_u32(&As[st + (wm * 32 + mt * 16 + (lane & 15)) * GP +
                                            ks * 32 + (lane >> 4) * 16]));
#pragma unroll
            for (int np = 0; np < 4; np++) {
                uint32_t bf[4];
                ldmx4(bf, smem_u32(&Bs[st + (wn * 64 + np * 16 + (lane & 15)) * GP +
                                        ks * 32 + (lane >> 4) * 16]));
#pragma unroll
                for (int mt = 0; mt < 2; mt++) {
                    mma_s8(acc[mt][np * 2],     af[mt], bf[0], bf[2]);
                    mma_s8(acc[mt][np * 2 + 1], af[mt], bf[1], bf[3]);
                }
            }
        }
        __syncthreads();
    }

    float alpha = g_alpha[3] * (1.0f / 127.0f);
#pragma unroll
    for (int mt = 0; mt < 2; mt++) {
        int r0 = t0 + wm * 32 + mt * 16 + (lane >> 2);
        int r1 = r0 + 8;
        float s0 = alpha * g_gamma_o[r0];
        float s1 = alpha * g_gamma_o[r1];
#pragma unroll
        for (int nt = 0; nt < 8; nt++) {
            int n = n0 + wn * 64 + nt * 8 + (lane & 3) * 2;
            float v00 = (float)acc[mt][nt][0] * s0, v01 = (float)acc[mt][nt][1] * s0;
            float v10 = (float)acc[mt][nt][2] * s1, v11 = (float)acc[mt][nt][3] * s1;
            const float* rr0 = resid + (size_t)r0 * HID + n;
            const float* rr1 = resid + (size_t)r1 * HID + n;
            *(float2*)&outf[(size_t)r0 * HID + n] = make_float2(v00 + rr0[0], v01 + rr0[1]);
            *(float2*)&outf[(size_t)r1 * HID + n] = make_float2(v10 + rr1[0], v11 + rr1[1]);
        }
    }
}

// ---------------- attention: flash, split-fp16 mma, cp.async 2-stage ----------
#define SPITCH 72
#define ATTN_SMEM (36864 * 2)   // 73728 B
__global__ __launch_bounds__(256) void attn_mma(float* __restrict__ out) {
    extern __shared__ __half ASM[];

    int tid = threadIdx.x;
    int warp = tid >> 5, lane = tid & 31;
    int qt = blockIdx.x;
    int bh = blockIdx.y;
    int b = bh / NQH, h = bh % NQH;
    int kvh = h / (NQH / NKVH);

    size_t qoff = ((size_t)(b * NQH + h) * SEQ + qt * 128) * HD;
    size_t kvoff = (size_t)(b * NKVH + kvh) * SEQ * HD;
    const __half* gbuf[4] = { g_kh + kvoff, g_kl + kvoff, g_vh + kvoff, g_vl + kvoff };

    __half* Qh = ASM;
    __half* Ql = ASM + 9216;
#pragma unroll
    for (int i = 0; i < 4; i++) {
        int slot = tid + i * 256;
        int r = slot >> 3, seg = slot & 7;
        *(float4*)&Qh[r * SPITCH + seg * 8] = *(const float4*)&g_qh[qoff + r * 64 + seg * 8];
        *(float4*)&Ql[r * SPITCH + seg * 8] = *(const float4*)&g_ql[qoff + r * 64 + seg * 8];
    }
    __syncthreads();

    // prefetch kt=0 into stage 1
    {
        __half* sb = ASM + 18432;
#pragma unroll
        for (int i = 0; i < 8; i++) {
            int slot = tid + i * 256;
            int bufi = slot >> 9, r = (slot >> 3) & 63, seg = slot & 7;
            cp16(&sb[bufi * 4608 + r * SPITCH + seg * 8], &gbuf[bufi][r * 64 + seg * 8]);
        }
        cp_commit();
    }

    uint32_t qah[4][4], qal[4][4];
    int m0 = warp * 16;
#pragma unroll
    for (int kc = 0; kc < 4; kc++) {
        int r = m0 + (lane & 15), c = kc * 16 + (lane >> 4) * 8;
        ldmx4(qah[kc], smem_u32(&Qh[r * SPITCH + c]));
        ldmx4(qal[kc], smem_u32(&Ql[r * SPITCH + c]));
    }
    __syncthreads();

    float oacc[8][4];
#pragma unroll
    for (int nt = 0; nt < 8; nt++)
#pragma unroll
        for (int i = 0; i < 4; i++) oacc[nt][i] = 0.0f;
    float mrow0 = -1e30f, mrow1 = -1e30f, lrow0 = 0.0f, lrow1 = 0.0f;

    for (int kt = 0; kt < 8; kt++) {
        if (kt < 7) {
            __half* sb = ASM + (kt & 1) * 18432;
#pragma unroll
            for (int i = 0; i < 8; i++) {
                int slot = tid + i * 256;
                int bufi = slot >> 9, r = (slot >> 3) & 63, seg = slot & 7;
                cp16(&sb[bufi * 4608 + r * SPITCH + seg * 8],
                     &gbuf[bufi][((kt + 1) * 64 + r) * 64 + seg * 8]);
            }
            cp_commit();
            cp_wait<1>();
        } else {
            cp_wait<0>();
        }
        __syncthreads();
        __half* sb = ASM + ((kt + 1) & 1) * 18432;
        __half* Khs = sb;
        __half* Kls = sb + 4608;
        __half* Vhs = sb + 9216;
        __half* Vls = sb + 13824;

        float sacc[8][4];
#pragma unroll
        for (int nt = 0; nt < 8; nt++)
#pragma unroll
            for (int i = 0; i < 4; i++) sacc[nt][i] = 0.0f;
        int g = lane >> 3;
        int n_off = (g >= 2) ? 8 : 0, k_off = (g & 1) * 8;
#pragma unroll
        for (int nt2 = 0; nt2 < 4; nt2++) {
#pragma unroll
            for (int kc = 0; kc < 4; kc++) {
                uint32_t kbh[4], kbl[4];
                int r = nt2 * 16 + n_off + (lane & 7), c = kc * 16 + k_off;
                ldmx4(kbh, smem_u32(&Khs[r * SPITCH + c]));
                ldmx4(kbl, smem_u32(&Kls[r * SPITCH + c]));
                mma_f16(sacc[nt2 * 2],     qah[kc], kbh[0], kbh[1]);
                mma_f16(sacc[nt2 * 2],     qah[kc], kbl[0], kbl[1]);
                mma_f16(sacc[nt2 * 2],     qal[kc], kbh[0], kbh[1]);
                mma_f16(sacc[nt2 * 2 + 1], qah[kc], kbh[2], kbh[3]);
                mma_f16(sacc[nt2 * 2 + 1], qah[kc], kbl[2], kbl[3]);
                mma_f16(sacc[nt2 * 2 + 1], qal[kc], kbh[2], kbh[3]);
            }
        }

        float mx0 = -1e30f, mx1 = -1e30f;
#pragma unroll
        for (int nt = 0; nt < 8; nt++) {
            mx0 = fmaxf(mx0, fmaxf(sacc[nt][0], sacc[nt][1]));
            mx1 = fmaxf(mx1, fmaxf(sacc[nt][2], sacc[nt][3]));
        }
        mx0 = fmaxf(mx0, __shfl_xor_sync(0xffffffffu, mx0, 1));
        mx0 = fmaxf(mx0, __shfl_xor_sync(0xffffffffu, mx0, 2));
        mx1 = fmaxf(mx1, __shfl_xor_sync(0xffffffffu, mx1, 1));
        mx1 = fmaxf(mx1, __shfl_xor_sync(0xffffffffu, mx1, 2));
        float mn0 = fmaxf(mrow0, mx0), mn1 = fmaxf(mrow1, mx1);
        float e0 = __expf(mrow0 - mn0), e1 = __expf(mrow1 - mn1);
        mrow0 = mn0; mrow1 = mn1;

        float sum0 = 0.0f, sum1 = 0.0f;
        uint32_t pah[4][4], pal[4][4];
#pragma unroll
        for (int kc2 = 0; kc2 < 4; kc2++) {
            int nta = kc2 * 2, ntb = nta + 1;
            float p[8];
            p[0] = __expf(sacc[nta][0] - mn0); p[1] = __expf(sacc[nta][1] - mn0);
            p[2] = __expf(sacc[nta][2] - mn1); p[3] = __expf(sacc[nta][3] - mn1);
            p[4] = __expf(sacc[ntb][0] - mn0); p[5] = __expf(sacc[ntb][1] - mn0);
            p[6] = __expf(sacc[ntb][2] - mn1); p[7] = __expf(sacc[ntb][3] - mn1);
            __half ph[8], pl[8];
#pragma unroll
            for (int i = 0; i < 8; i++) split_h(p[i], ph[i], pl[i]);
            sum0 += p[0] + p[1] + p[4] + p[5];
            sum1 += p[2] + p[3] + p[6] + p[7];
            pah[kc2][0] = pack_h2(ph[0], ph[1]); pal[kc2][0] = pack_h2(pl[0], pl[1]);
            pah[kc2][1] = pack_h2(ph[2], ph[3]); pal[kc2][1] = pack_h2(pl[2], pl[3]);
            pah[kc2][2] = pack_h2(ph[4], ph[5]); pal[kc2][2] = pack_h2(pl[4], pl[5]);
            pah[kc2][3] = pack_h2(ph[6], ph[7]); pal[kc2][3] = pack_h2(pl[6], pl[7]);
        }
        sum0 += __shfl_xor_sync(0xffffffffu, sum0, 1);
        sum0 += __shfl_xor_sync(0xffffffffu, sum0, 2);
        sum1 += __shfl_xor_sync(0xffffffffu, sum1, 1);
        sum1 += __shfl_xor_sync(0xffffffffu, sum1, 2);
        lrow0 = lrow0 * e0 + sum0;
        lrow1 = lrow1 * e1 + sum1;

#pragma unroll
        for (int nt = 0; nt < 8; nt++) {
            oacc[nt][0] *= e0; oacc[nt][1] *= e0;
            oacc[nt][2] *= e1; oacc[nt][3] *= e1;
        }

#pragma unroll
        for (int kc2 = 0; kc2 < 4; kc2++) {
#pragma unroll
            for (int nt2 = 0; nt2 < 4; nt2++) {
                uint32_t vbh[4], vbl[4];
                int r = kc2 * 16 + (g & 1) * 8 + (lane & 7);
                int c = nt2 * 16 + ((g >= 2) ? 8 : 0);
                ldmx4t(vbh, smem_u32(&Vhs[r * SPITCH + c]));
                ldmx4t(vbl, smem_u32(&Vls[r * SPITCH + c]));
                mma_f16(oacc[nt2 * 2],     pah[kc2], vbh[0], vbh[1]);
                mma_f16(oacc[nt2 * 2],     pah[kc2], vbl[0], vbl[1]);
                mma_f16(oacc[nt2 * 2],     pal[kc2], vbh[0], vbh[1]);
                mma_f16(oacc[nt2 * 2 + 1], pah[kc2], vbh[2], vbh[3]);
                mma_f16(oacc[nt2 * 2 + 1], pah[kc2], vbl[2], vbl[3]);
                mma_f16(oacc[nt2 * 2 + 1], pal[kc2], vbh[2], vbh[3]);
            }
        }
        __syncthreads();
    }

    float inv0 = 1.0f / lrow0, inv1 = 1.0f / lrow1;
    int r0 = qt * 128 + m0 + (lane >> 2);
    int r1 = r0 + 8;
#pragma unroll
    for (int nt = 0; nt < 8; nt++) {
        int col = h * HD + nt * 8 + (lane & 3) * 2;
        float2 v0 = make_float2(oacc[nt][0] * inv0, oacc[nt][1] * inv0);
        float2 v1 = make_float2(oacc[nt][2] * inv1, oacc[nt][3] * inv1);
        *(float2*)&out[((size_t)b * SEQ + r0) * HID + col] = v0;
        *(float2*)&out[((size_t)b * SEQ + r1) * HID + col] = v1;
    }
}

// ---------------- launch ----------------
extern "C" void kernel_launch(void* const* d_in, const int* in_sizes, int n_in,
                              void* d_out, int out_size) {
    const float* x      = (const float*)d_in[0];
    const float* norm_w = (const float*)d_in[1];
    const float* q_w    = (const float*)d_in[2];
    const float* q_g    = (const float*)d_in[3];
    const float* k_w    = (const float*)d_in[4];
    const float* k_g    = (const float*)d_in[5];
    const float* v_w    = (const float*)d_in[6];
    const float* v_g    = (const float*)d_in[7];
    const float* o_w    = (const float*)d_in[8];
    const float* o_g    = (const float*)d_in[9];
    float* out = (float*)d_out;

    void* p_att;
    cudaGetSymbolAddress(&p_att, g_att);

    const int GEMM_SMEM = 4 * GSTAGE;
    cudaFuncSetAttribute(gemm_qkv, cudaFuncAttributeMaxDynamicSharedMemorySize, GEMM_SMEM);
    cudaFuncSetAttribute(gemm_o, cudaFuncAttributeMaxDynamicSharedMemorySize, GEMM_SMEM);
    cudaFuncSetAttribute(attn_mma, cudaFuncAttributeMaxDynamicSharedMemorySize, ATTN_SMEM);

    // 1. weight alphas + rope tables (fused)
    prep_all<<<68, 1024>>>(q_w, k_w, v_w, o_w);

    // 2. weight ternary quant
    wquant_all<<<(2 * HID * HID + 2 * KVDIM * HID + 255) / 256, 256>>>(q_w, k_w, v_w, o_w);

    // 3. activation double-rmsnorm + int8 quant
    act_quant_qkv<<<T_TOKENS / 8, 256>>>(x, norm_w, q_g, k_g, v_g);

    // 4. fused QKV GEMMs (int8 TC -> split fp16 hi/lo, rope fused)  [profiled]
    gemm_qkv<<<896, 256, GEMM_SMEM>>>();

    // 5. attention
    attn_mma<<<dim3(SEQ / 128, BATCH * NQH), 256, ATTN_SMEM>>>((float*)p_att);

    // 6. O-proj quant + GEMM + residual
    act_quant_o<<<T_TOKENS / 8, 256>>>(o_g);
    gemm_o<<<dim3(128, 5), 256, GEMM_SMEM>>>(out, x);
}